// round 11
// baseline (speedup 1.0000x reference)
#include <cuda_runtime.h>
#include <cuda_bf16.h>
#include <math.h>
#include <stdint.h>

// Problem constants
#define Bc  2
#define Tc  2048
#define Dc  1024
#define Hc  16
#define HDc 64
#define Mc  (Bc * Tc)          // 4096
#define DD  (Dc * Dc)
#define ATTN_SCALE 0.125f

// Scratch (bf16 hi/lo everywhere)
static __device__ __align__(16) __nv_bfloat16 g_xhi[Mc * Dc], g_xlo[Mc * Dc];
static __device__ __align__(16) __nv_bfloat16 g_whi[4][DD], g_wlo[4][DD];
static __device__ __align__(16) __nv_bfloat16 g_qh[Mc * Dc], g_ql[Mc * Dc];
static __device__ __align__(16) __nv_bfloat16 g_kh[Mc * Dc], g_kl[Mc * Dc];
static __device__ __align__(16) __nv_bfloat16 g_vh[Mc * Dc], g_vl[Mc * Dc];
static __device__ __align__(16) __nv_bfloat16 g_yhi[Mc * Dc], g_ylo[Mc * Dc];

// ---------------------------------------------------------------------------
// PTX helpers — base-target-safe (mma.sync / ldmatrix / cp.async)
// ---------------------------------------------------------------------------
__device__ __forceinline__ uint32_t smem_u32(const void* p) {
    uint32_t a;
    asm("{ .reg .u64 t; cvta.to.shared.u64 t, %1; cvt.u32.u64 %0, t; }" : "=r"(a) : "l"(p));
    return a;
}
__device__ __forceinline__ void ldm_x4(uint32_t& r0, uint32_t& r1, uint32_t& r2,
                                       uint32_t& r3, uint32_t addr) {
    asm volatile("ldmatrix.sync.aligned.m8n8.x4.shared.b16 {%0,%1,%2,%3}, [%4];"
                 : "=r"(r0), "=r"(r1), "=r"(r2), "=r"(r3) : "r"(addr));
}
__device__ __forceinline__ void ldm_x4t(uint32_t& r0, uint32_t& r1, uint32_t& r2,
                                        uint32_t& r3, uint32_t addr) {
    asm volatile("ldmatrix.sync.aligned.m8n8.x4.trans.shared.b16 {%0,%1,%2,%3}, [%4];"
                 : "=r"(r0), "=r"(r1), "=r"(r2), "=r"(r3) : "r"(addr));
}
__device__ __forceinline__ void mma16816(float* d, const uint32_t* a, const uint32_t* b) {
    asm volatile("mma.sync.aligned.m16n8k16.row.col.f32.bf16.bf16.f32 "
                 "{%0,%1,%2,%3}, {%4,%5,%6,%7}, {%8,%9}, {%0,%1,%2,%3};"
                 : "+f"(d[0]), "+f"(d[1]), "+f"(d[2]), "+f"(d[3])
                 : "r"(a[0]), "r"(a[1]), "r"(a[2]), "r"(a[3]), "r"(b[0]), "r"(b[1]));
}
__device__ __forceinline__ void cp16(uint32_t dst, const void* src) {
    asm volatile("cp.async.cg.shared.global [%0], [%1], 16;" :: "r"(dst), "l"(src));
}
__device__ __forceinline__ void cp_commit() {
    asm volatile("cp.async.commit_group;" ::: "memory");
}
template <int N>
__device__ __forceinline__ void cp_wait() {
    asm volatile("cp.async.wait_group %0;" :: "n"(N) : "memory");
}
__device__ __forceinline__ uint32_t pack_hi2(float a, float b) {
    __nv_bfloat162 v = __floats2bfloat162_rn(a, b);
    return *(uint32_t*)&v;
}

// ---------------------------------------------------------------------------
// Fused fp32 -> bf16 hi/lo split: x + all 4 weights in one launch.
// ---------------------------------------------------------------------------
#define NX4 (Mc * Dc / 4)
#define NW4 (DD / 4)

__global__ void __launch_bounds__(256)
split_all(const float* __restrict__ x,
          const float* __restrict__ w0, const float* __restrict__ w1,
          const float* __restrict__ w2, const float* __restrict__ w3,
          __nv_bfloat16* __restrict__ xhi, __nv_bfloat16* __restrict__ xlo,
          __nv_bfloat16* __restrict__ whi, __nv_bfloat16* __restrict__ wlo)
{
    const size_t c = (size_t)blockIdx.x * 256 + threadIdx.x;
    const float* src;
    __nv_bfloat16 *ho, *lo_;
    if (c < NX4) {
        src = x + c * 4;
        ho = xhi + c * 4; lo_ = xlo + c * 4;
    } else {
        const size_t r = c - NX4;
        const int w = (int)(r >> 18);
        const size_t l = (r & (NW4 - 1)) * 4;
        const float* ws = (w == 0) ? w0 : (w == 1) ? w1 : (w == 2) ? w2 : w3;
        src = ws + l;
        ho = whi + (size_t)w * DD + l; lo_ = wlo + (size_t)w * DD + l;
    }
    const float4 v = *(const float4*)src;
    const __nv_bfloat16 h0 = __float2bfloat16(v.x);
    const __nv_bfloat16 h1 = __float2bfloat16(v.y);
    const __nv_bfloat16 h2 = __float2bfloat16(v.z);
    const __nv_bfloat16 h3 = __float2bfloat16(v.w);
    __nv_bfloat162 ha, hb, la, lb;
    ha.x = h0; ha.y = h1; hb.x = h2; hb.y = h3;
    la.x = __float2bfloat16(v.x - __bfloat162float(h0));
    la.y = __float2bfloat16(v.y - __bfloat162float(h1));
    lb.x = __float2bfloat16(v.z - __bfloat162float(h2));
    lb.y = __float2bfloat16(v.w - __bfloat162float(h3));
    ((__nv_bfloat162*)ho)[0] = ha; ((__nv_bfloat162*)ho)[1] = hb;
    ((__nv_bfloat162*)lo_)[0] = la; ((__nv_bfloat162*)lo_)[1] = lb;
}

// ---------------------------------------------------------------------------
// GEMM (R10 known-good): CTA tile 128x64, K-block 64, 2-stage cp.async,
// stage = A(32K) + W(16K) = 48 KB -> 96 KB -> 2 CTAs/SM.
// MODE 0: fp32 out. MODE 1: flat N=3072 QKV -> head-layout bf16 hi/lo.
// ---------------------------------------------------------------------------
#define RC_STAGE 49152
#define RC_SMEM  (2 * RC_STAGE)

template <int MODE>
__global__ void __launch_bounds__(256, 2)
gemm_rc(const __nv_bfloat16* __restrict__ Ahi, const __nv_bfloat16* __restrict__ Alo,
        const __nv_bfloat16* __restrict__ Wh, const __nv_bfloat16* __restrict__ Wl,
        const float* __restrict__ b0, const float* __restrict__ b1,
        const float* __restrict__ b2, float* __restrict__ C,
        __nv_bfloat16* __restrict__ qh, __nv_bfloat16* __restrict__ ql,
        __nv_bfloat16* __restrict__ kh, __nv_bfloat16* __restrict__ kl,
        __nv_bfloat16* __restrict__ vh, __nv_bfloat16* __restrict__ vl)
{
    extern __shared__ char smem[];
    const uint32_t sb = smem_u32(smem);
    const int tid = threadIdx.x;
    const int lane = tid & 31;
    const int wid = tid >> 5;
    const int m0 = blockIdx.y * 128;
    const int n0 = blockIdx.x * 64;
    const int wm = (wid & 1) * 64;
    const int wn = (wid >> 1) * 16;

    auto issue = [&](int kb, int bufo) {
#pragma unroll
        for (int it = 0; it < 8; it++) {
            const int idx = it * 256 + tid;
            const int tile = idx >> 10;
            const int r = (idx >> 3) & 127;
            const int ch = idx & 7;
            const uint32_t dst = sb + bufo + tile * 16384 + r * 128 +
                                 ((ch * 16) ^ ((r & 7) << 4));
            const __nv_bfloat16* src = tile ? Alo : Ahi;
            cp16(dst, src + (size_t)(m0 + r) * Dc + kb * 64 + ch * 8);
        }
#pragma unroll
        for (int it = 0; it < 4; it++) {
            const int idx = it * 256 + tid;
            const int wt = idx >> 9;
            const int r = (idx >> 3) & 63;
            const int ch = idx & 7;
            const uint32_t dst = sb + bufo + 32768 + wt * 8192 + r * 128 +
                                 ((ch * 16) ^ ((r & 7) << 4));
            const __nv_bfloat16* src = wt ? Wl : Wh;
            cp16(dst, src + (size_t)(n0 + r) * Dc + kb * 64 + ch * 8);
        }
        cp_commit();
    };

    const int g = lane >> 3;
    const int lr = lane & 7;
    int aRow[4];
    uint32_t aSw[4];
#pragma unroll
    for (int mf = 0; mf < 4; mf++) {
        aRow[mf] = wm + mf * 16 + ((g & 1) ? 8 : 0) + lr;
        aSw[mf] = (uint32_t)((aRow[mf] & 7) << 4);
    }
    const uint32_t aKext = (g >= 2) ? 16u : 0u;
    const int bRow = wn + ((g >= 2) ? 8 : 0) + lr;
    const uint32_t bSw = (uint32_t)((bRow & 7) << 4);
    const uint32_t bKext = (g & 1) ? 16u : 0u;

    float acc[4][2][4];
#pragma unroll
    for (int mf = 0; mf < 4; mf++)
#pragma unroll
        for (int nf = 0; nf < 2; nf++)
#pragma unroll
            for (int q = 0; q < 4; q++) acc[mf][nf][q] = 0.0f;

    issue(0, 0);

    for (int kb = 0; kb < 16; kb++) {
        const int bufo = (kb & 1) * RC_STAGE;
        cp_wait<0>();
        __syncthreads();
        if (kb < 15) issue(kb + 1, RC_STAGE - bufo);

        const uint32_t bA = sb + bufo;
        const uint32_t bW = bA + 32768;
#pragma unroll
        for (int ks = 0; ks < 4; ks++) {
            uint32_t ah[4][4], al[4][4];
#pragma unroll
            for (int mf = 0; mf < 4; mf++) {
                const uint32_t off = (uint32_t)(aRow[mf] * 128) +
                                     (((uint32_t)(ks * 32) + aKext) ^ aSw[mf]);
                ldm_x4(ah[mf][0], ah[mf][1], ah[mf][2], ah[mf][3], bA + off);
                ldm_x4(al[mf][0], al[mf][1], al[mf][2], al[mf][3], bA + 16384 + off);
            }
            const uint32_t boff = (uint32_t)(bRow * 128) +
                                  (((uint32_t)(ks * 32) + bKext) ^ bSw);
            uint32_t bh[2][2], bl[2][2];
            ldm_x4(bh[0][0], bh[0][1], bh[1][0], bh[1][1], bW + boff);
            ldm_x4(bl[0][0], bl[0][1], bl[1][0], bl[1][1], bW + 8192 + boff);
#pragma unroll
            for (int mf = 0; mf < 4; mf++)
#pragma unroll
                for (int nf = 0; nf < 2; nf++) {
                    mma16816(acc[mf][nf], ah[mf], bh[nf]);
                    mma16816(acc[mf][nf], ah[mf], bl[nf]);
                    mma16816(acc[mf][nf], al[mf], bh[nf]);
                }
        }
    }

    const int tr = lane >> 2;
    const int tc2 = (lane & 3) * 2;

    if (MODE == 0) {
#pragma unroll
        for (int mf = 0; mf < 4; mf++)
#pragma unroll
            for (int nf = 0; nf < 2; nf++) {
                const int n = n0 + wn + nf * 8 + tc2;
                const float bb0 = b0[n], bb1 = b0[n + 1];
                const int mA = m0 + wm + mf * 16 + tr;
                const int mB = mA + 8;
                float2 vA, vB;
                vA.x = acc[mf][nf][0] + bb0; vA.y = acc[mf][nf][1] + bb1;
                vB.x = acc[mf][nf][2] + bb0; vB.y = acc[mf][nf][3] + bb1;
                *(float2*)(C + (size_t)mA * Dc + n) = vA;
                *(float2*)(C + (size_t)mB * Dc + n) = vB;
            }
    } else {
        const int w = n0 >> 10;
        const int nl0 = n0 & 1023;
        const float scl = (w == 0) ? ATTN_SCALE : 1.0f;
        const float* bias = (w == 0) ? b0 : (w == 1) ? b1 : b2;
        __nv_bfloat16* oh = (w == 0) ? qh : (w == 1) ? kh : vh;
        __nv_bfloat16* ol = (w == 0) ? ql : (w == 1) ? kl : vl;
#pragma unroll
        for (int mf = 0; mf < 4; mf++)
#pragma unroll
            for (int nf = 0; nf < 2; nf++) {
                const int n = nl0 + wn + nf * 8 + tc2;
                const float bb0 = bias[n], bb1 = bias[n + 1];
                const int mA = m0 + wm + mf * 16 + tr;
                const int mB = mA + 8;
                const float vA0 = (acc[mf][nf][0] + bb0) * scl;
                const float vA1 = (acc[mf][nf][1] + bb1) * scl;
                const float vB0 = (acc[mf][nf][2] + bb0) * scl;
                const float vB1 = (acc[mf][nf][3] + bb1) * scl;
                const int hh = n >> 6, hd = n & 63;
                const int bA = mA >> 11, tA = mA & 2047;
                const int bB = mB >> 11, tB = mB & 2047;
                const size_t oA = ((size_t)(bA * Hc + hh) * Tc + tA) * HDc + hd;
                const size_t oB = ((size_t)(bB * Hc + hh) * Tc + tB) * HDc + hd;
                __nv_bfloat162 hA = __floats2bfloat162_rn(vA0, vA1);
                __nv_bfloat162 hB = __floats2bfloat162_rn(vB0, vB1);
                __nv_bfloat162 lA, lB;
                lA.x = __float2bfloat16(vA0 - __bfloat162float(hA.x));
                lA.y = __float2bfloat16(vA1 - __bfloat162float(hA.y));
                lB.x = __float2bfloat16(vB0 - __bfloat162float(hB.x));
                lB.y = __float2bfloat16(vB1 - __bfloat162float(hB.y));
                *(__nv_bfloat162*)(oh + oA) = hA;
                *(__nv_bfloat162*)(oh + oB) = hB;
                *(__nv_bfloat162*)(ol + oA) = lA;
                *(__nv_bfloat162*)(ol + oB) = lB;
            }
    }
}

// ---------------------------------------------------------------------------
// Tensor-core causal flash attention. BQ=128 (16 q-rows/warp), BKV=64.
// 2-stage cp.async KV pipeline (Q 32 KB + 2 x 32 KB = 96 KB) -> 2 CTAs/SM.
// One barrier per tile: { cp_wait; sync; issue(next); compute }.
// ---------------------------------------------------------------------------
#define FL_SMEM (32768 + 2 * 32768)

__global__ void __launch_bounds__(256, 2)
flash_mma(const __nv_bfloat16* __restrict__ Qh_, const __nv_bfloat16* __restrict__ Ql_,
          const __nv_bfloat16* __restrict__ Kh_, const __nv_bfloat16* __restrict__ Kl_,
          const __nv_bfloat16* __restrict__ Vh_, const __nv_bfloat16* __restrict__ Vl_,
          __nv_bfloat16* __restrict__ Yhi, __nv_bfloat16* __restrict__ Ylo)
{
    extern __shared__ char smem[];
    const uint32_t sb = smem_u32(smem);
    const int tid = threadIdx.x;
    const int lane = tid & 31;
    const int w = tid >> 5;
    const int qi = (int)(gridDim.x - 1) - (int)blockIdx.x;   // heavy tiles first
    const int q0 = qi * 128;
    const int h = blockIdx.y, b = blockIdx.z;
    const size_t base = (size_t)(b * Hc + h) * Tc * HDc;
    const __nv_bfloat16* Qh = Qh_ + base;
    const __nv_bfloat16* Ql = Ql_ + base;
    const __nv_bfloat16* Kh = Kh_ + base;
    const __nv_bfloat16* Kl = Kl_ + base;
    const __nv_bfloat16* Vh = Vh_ + base;
    const __nv_bfloat16* Vl = Vl_ + base;

    // Q tiles (Qh at 0, Ql at 16384) — first commit group
#pragma unroll
    for (int it = 0; it < 4; it++) {
        const int idx = it * 256 + tid;
        const int r = idx >> 3;
        const int ch = idx & 7;
        const uint32_t off = r * 128 + ((ch * 16) ^ ((r & 7) << 4));
        const size_t gi = (size_t)(q0 + r) * HDc + ch * 8;
        cp16(sb + off, Qh + gi);
        cp16(sb + 16384 + off, Ql + gi);
    }
    cp_commit();

    auto issueKV = [&](int t) {
        const int k0 = t * 64;
        const uint32_t so = sb + 32768 + (t & 1) * 32768;
#pragma unroll
        for (int it = 0; it < 2; it++) {
            const int idx = it * 256 + tid;
            const int r = idx >> 3;
            const int ch = idx & 7;
            const uint32_t off = r * 128 + ((ch * 16) ^ ((r & 7) << 4));
            const size_t gi = (size_t)(k0 + r) * HDc + ch * 8;
            cp16(so + off,         Kh + gi);
            cp16(so + 8192 + off,  Kl + gi);
            cp16(so + 16384 + off, Vh + gi);
            cp16(so + 24576 + off, Vl + gi);
        }
        cp_commit();
    };

    const int g = lane >> 3;
    const int lr = lane & 7;
    const int aRow = w * 16 + ((g & 1) ? 8 : 0) + lr;
    const uint32_t aSw = (uint32_t)((aRow & 7) << 4);
    const uint32_t aKext = (g >= 2) ? 16u : 0u;
    const int bRowBase = ((g >= 2) ? 8 : 0) + lr;
    const uint32_t bKext = (g & 1) ? 16u : 0u;
    const int vRow = lane & 15;
    const uint32_t vDext = (lane & 16) ? 16u : 0u;

    const int tr = lane >> 2;
    const int tc2 = (lane & 3) * 2;
    const int rowg0 = q0 + w * 16 + tr;
    const int rowg1 = rowg0 + 8;

    float mL[2] = { -INFINITY, -INFINITY };
    float lL[2] = { 0.0f, 0.0f };
    float o[8][4];
#pragma unroll
    for (int j = 0; j < 8; j++)
#pragma unroll
        for (int q = 0; q < 4; q++) o[j][q] = 0.0f;

    const int nt = q0 / 64 + 2;
    issueKV(0);

    for (int t = 0; t < nt; t++) {
        const int k0 = t * 64;
        cp_wait<0>();                 // Q + all issued KV groups (incl. KV_t) landed
        __syncthreads();              // visibility across warps + prior reads done
        if (t + 1 < nt) issueKV(t + 1);   // targets buf (t+1)&1 = buf read at t-1

        if (k0 <= q0 + w * 16 + 15) {
            const uint32_t so = sb + 32768 + (t & 1) * 32768;
            float s[8][4];
#pragma unroll
            for (int j = 0; j < 8; j++)
#pragma unroll
                for (int q = 0; q < 4; q++) s[j][q] = 0.0f;

            // S = Q K^T (3-term)
#pragma unroll
            for (int ks = 0; ks < 4; ks++) {
                const uint32_t ka = (uint32_t)(ks * 32) + aKext;
                uint32_t qh4[4], ql4[4];
                const uint32_t qoff = (uint32_t)(aRow * 128) + (ka ^ aSw);
                ldm_x4(qh4[0], qh4[1], qh4[2], qh4[3], sb + qoff);
                ldm_x4(ql4[0], ql4[1], ql4[2], ql4[3], sb + 16384 + qoff);
#pragma unroll
                for (int p = 0; p < 4; p++) {
                    const int row = p * 16 + bRowBase;
                    const uint32_t off = (uint32_t)(row * 128) +
                        (((uint32_t)(ks * 32) + bKext) ^ ((uint32_t)((row & 7) << 4)));
                    uint32_t kh2[2][2], kl2[2][2];
                    ldm_x4(kh2[0][0], kh2[0][1], kh2[1][0], kh2[1][1], so + off);
                    ldm_x4(kl2[0][0], kl2[0][1], kl2[1][0], kl2[1][1], so + 8192 + off);
#pragma unroll
                    for (int u = 0; u < 2; u++) {
                        mma16816(s[2 * p + u], qh4, kh2[u]);
                        mma16816(s[2 * p + u], qh4, kl2[u]);
                        mma16816(s[2 * p + u], ql4, kh2[u]);
                    }
                }
            }

            // Causal mask
            if (k0 + 63 > q0 + w * 16) {
#pragma unroll
                for (int j = 0; j < 8; j++) {
                    const int c = k0 + j * 8 + tc2;
                    if (c > rowg0)     s[j][0] = -INFINITY;
                    if (c + 1 > rowg0) s[j][1] = -INFINITY;
                    if (c > rowg1)     s[j][2] = -INFINITY;
                    if (c + 1 > rowg1) s[j][3] = -INFINITY;
                }
            }

            // Online softmax
#pragma unroll
            for (int half = 0; half < 2; half++) {
                const int i0 = half * 2;
                float mx = -INFINITY;
#pragma unroll
                for (int j = 0; j < 8; j++)
                    mx = fmaxf(mx, fmaxf(s[j][i0], s[j][i0 + 1]));
                mx = fmaxf(mx, __shfl_xor_sync(0xffffffffu, mx, 1));
                mx = fmaxf(mx, __shfl_xor_sync(0xffffffffu, mx, 2));
                const float mn = fmaxf(mL[half], mx);
                const float alpha = __expf(mL[half] - mn);
                float rs = 0.0f;
#pragma unroll
                for (int j = 0; j < 8; j++) {
                    const float p0 = __expf(s[j][i0] - mn);
                    const float p1 = __expf(s[j][i0 + 1] - mn);
                    s[j][i0] = p0; s[j][i0 + 1] = p1;
                    rs += p0 + p1;
                }
                rs += __shfl_xor_sync(0xffffffffu, rs, 1);
                rs += __shfl_xor_sync(0xffffffffu, rs, 2);
                lL[half] = lL[half] * alpha + rs;
                mL[half] = mn;
#pragma unroll
                for (int j = 0; j < 8; j++) {
                    o[j][i0] *= alpha;
                    o[j][i0 + 1] *= alpha;
                }
            }

            // O += P V (3-term)
#pragma unroll
            for (int ks = 0; ks < 4; ks++) {
                const int j0 = 2 * ks, j1 = j0 + 1;
                uint32_t pha[4], pla[4];
                {
                    const float a0 = s[j0][0], a1 = s[j0][1];
                    const float a2 = s[j0][2], a3 = s[j0][3];
                    const float c0 = s[j1][0], c1 = s[j1][1];
                    const float c2 = s[j1][2], c3 = s[j1][3];
                    pha[0] = pack_hi2(a0, a1); pha[1] = pack_hi2(a2, a3);
                    pha[2] = pack_hi2(c0, c1); pha[3] = pack_hi2(c2, c3);
                    const __nv_bfloat162* hp0 = (const __nv_bfloat162*)&pha[0];
                    const __nv_bfloat162* hp1 = (const __nv_bfloat162*)&pha[1];
                    const __nv_bfloat162* hp2 = (const __nv_bfloat162*)&pha[2];
                    const __nv_bfloat162* hp3 = (const __nv_bfloat162*)&pha[3];
                    pla[0] = pack_hi2(a0 - __bfloat162float(hp0->x), a1 - __bfloat162float(hp0->y));
                    pla[1] = pack_hi2(a2 - __bfloat162float(hp1->x), a3 - __bfloat162float(hp1->y));
                    pla[2] = pack_hi2(c0 - __bfloat162float(hp2->x), c1 - __bfloat162float(hp2->y));
                    pla[3] = pack_hi2(c2 - __bfloat162float(hp3->x), c3 - __bfloat162float(hp3->y));
                }
                const int vr = ks * 16 + vRow;
                const uint32_t vsw = (uint32_t)((vr & 7) << 4);
#pragma unroll
                for (int pp = 0; pp < 4; pp++) {
                    const uint32_t dbyte = (uint32_t)(pp * 32) + vDext;
                    const uint32_t off = (uint32_t)(vr * 128) + (dbyte ^ vsw);
                    uint32_t vh2[2][2], vl2[2][2];
                    ldm_x4t(vh2[0][0], vh2[0][1], vh2[1][0], vh2[1][1], so + 16384 + off);
                    ldm_x4t(vl2[0][0], vl2[0][1], vl2[1][0], vl2[1][1], so + 24576 + off);
#pragma unroll
                    for (int u = 0; u < 2; u++) {
                        mma16816(o[2 * pp + u], pha, vh2[u]);
                        mma16816(o[2 * pp + u], pha, vl2[u]);
                        mma16816(o[2 * pp + u], pla, vh2[u]);
                    }
                }
            }
        }
    }

    // Epilogue: y (B,T,D) bf16 hi/lo
    const float inv0 = 1.0f / lL[0];
    const float inv1 = 1.0f / lL[1];
#pragma unroll
    for (int j = 0; j < 8; j++) {
        const int col = h * HDc + j * 8 + tc2;
        const float y00 = o[j][0] * inv0, y01 = o[j][1] * inv0;
        const float y10 = o[j][2] * inv1, y11 = o[j][3] * inv1;
        const size_t o0 = ((size_t)(b * Tc + rowg0)) * Dc + col;
        const size_t o1 = ((size_t)(b * Tc + rowg1)) * Dc + col;
        __nv_bfloat162 h0 = __floats2bfloat162_rn(y00, y01);
        __nv_bfloat162 h1 = __floats2bfloat162_rn(y10, y11);
        __nv_bfloat162 l0, l1;
        l0.x = __float2bfloat16(y00 - __bfloat162float(h0.x));
        l0.y = __float2bfloat16(y01 - __bfloat162float(h0.y));
        l1.x = __float2bfloat16(y10 - __bfloat162float(h1.x));
        l1.y = __float2bfloat16(y11 - __bfloat162float(h1.y));
        *(__nv_bfloat162*)(Yhi + o0) = h0;
        *(__nv_bfloat162*)(Yhi + o1) = h1;
        *(__nv_bfloat162*)(Ylo + o0) = l0;
        *(__nv_bfloat162*)(Ylo + o1) = l1;
    }
}

// ---------------------------------------------------------------------------
// Launch
// ---------------------------------------------------------------------------
extern "C" void kernel_launch(void* const* d_in, const int* in_sizes, int n_in,
                              void* d_out, int out_size)
{
    const float* x  = (const float*)d_in[0];
    // d_in[1]: boolean causal mask (applied analytically)
    const float* Wq = (const float*)d_in[2];
    const float* bq = (const float*)d_in[3];
    const float* Wk = (const float*)d_in[4];
    const float* bk = (const float*)d_in[5];
    const float* Wv = (const float*)d_in[6];
    const float* bv = (const float*)d_in[7];
    const float* Wo = (const float*)d_in[8];
    const float* bo = (const float*)d_in[9];
    float* out = (float*)d_out;

    __nv_bfloat16 *xhi, *xlo, *whi, *wlo, *yhi, *ylo;
    __nv_bfloat16 *qh, *ql, *kh, *kl, *vh, *vl;
    cudaGetSymbolAddress((void**)&xhi, g_xhi);
    cudaGetSymbolAddress((void**)&xlo, g_xlo);
    cudaGetSymbolAddress((void**)&whi, g_whi);
    cudaGetSymbolAddress((void**)&wlo, g_wlo);
    cudaGetSymbolAddress((void**)&yhi, g_yhi);
    cudaGetSymbolAddress((void**)&ylo, g_ylo);
    cudaGetSymbolAddress((void**)&qh,  g_qh);
    cudaGetSymbolAddress((void**)&ql,  g_ql);
    cudaGetSymbolAddress((void**)&kh,  g_kh);
    cudaGetSymbolAddress((void**)&kl,  g_kl);
    cudaGetSymbolAddress((void**)&vh,  g_vh);
    cudaGetSymbolAddress((void**)&vl,  g_vl);

    cudaFuncSetAttribute(gemm_rc<0>, cudaFuncAttributeMaxDynamicSharedMemorySize, RC_SMEM);
    cudaFuncSetAttribute(gemm_rc<1>, cudaFuncAttributeMaxDynamicSharedMemorySize, RC_SMEM);
    cudaFuncSetAttribute(flash_mma, cudaFuncAttributeMaxDynamicSharedMemorySize, FL_SMEM);

    // Fused splits: x + Wq,Wk,Wv,Wo -> bf16 hi/lo
    split_all<<<(NX4 + 4 * NW4) / 256, 256>>>(x, Wq, Wk, Wv, Wo, xhi, xlo, whi, wlo);

    // QKV as one flat N=3072 GEMM over concatenated weights
    gemm_rc<1><<<dim3(3 * Dc / 64, Mc / 128), 256, RC_SMEM>>>(
        xhi, xlo, whi, wlo, bq, bk, bv, nullptr,
        qh, ql, kh, kl, vh, vl);

    flash_mma<<<dim3(Tc / 128, Hc, Bc), 256, FL_SMEM>>>(qh, ql, kh, kl, vh, vl, yhi, ylo);

    gemm_rc<0><<<dim3(Dc / 64, Mc / 128), 256, RC_SMEM>>>(
        yhi, ylo, whi + 3 * (size_t)DD, wlo + 3 * (size_t)DD, bo, nullptr, nullptr, out,
        nullptr, nullptr, nullptr, nullptr, nullptr, nullptr);
}

// round 12
// speedup vs baseline: 1.0561x; 1.0561x over previous
#include <cuda_runtime.h>
#include <cuda_bf16.h>
#include <math.h>
#include <stdint.h>

// Problem constants
#define Bc  2
#define Tc  2048
#define Dc  1024
#define Hc  16
#define HDc 64
#define Mc  (Bc * Tc)          // 4096
#define DD  (Dc * Dc)
#define ATTN_SCALE 0.125f

// Scratch (bf16 hi/lo everywhere)
static __device__ __align__(16) __nv_bfloat16 g_xhi[Mc * Dc], g_xlo[Mc * Dc];
static __device__ __align__(16) __nv_bfloat16 g_whi[4][DD], g_wlo[4][DD];
static __device__ __align__(16) __nv_bfloat16 g_qh[Mc * Dc], g_ql[Mc * Dc];
static __device__ __align__(16) __nv_bfloat16 g_kh[Mc * Dc], g_kl[Mc * Dc];
static __device__ __align__(16) __nv_bfloat16 g_vh[Mc * Dc], g_vl[Mc * Dc];
static __device__ __align__(16) __nv_bfloat16 g_yhi[Mc * Dc], g_ylo[Mc * Dc];

// ---------------------------------------------------------------------------
// PTX helpers — base-target-safe (mma.sync / ldmatrix / cp.async)
// ---------------------------------------------------------------------------
__device__ __forceinline__ uint32_t smem_u32(const void* p) {
    uint32_t a;
    asm("{ .reg .u64 t; cvta.to.shared.u64 t, %1; cvt.u32.u64 %0, t; }" : "=r"(a) : "l"(p));
    return a;
}
__device__ __forceinline__ void ldm_x4(uint32_t& r0, uint32_t& r1, uint32_t& r2,
                                       uint32_t& r3, uint32_t addr) {
    asm volatile("ldmatrix.sync.aligned.m8n8.x4.shared.b16 {%0,%1,%2,%3}, [%4];"
                 : "=r"(r0), "=r"(r1), "=r"(r2), "=r"(r3) : "r"(addr));
}
__device__ __forceinline__ void ldm_x4t(uint32_t& r0, uint32_t& r1, uint32_t& r2,
                                        uint32_t& r3, uint32_t addr) {
    asm volatile("ldmatrix.sync.aligned.m8n8.x4.trans.shared.b16 {%0,%1,%2,%3}, [%4];"
                 : "=r"(r0), "=r"(r1), "=r"(r2), "=r"(r3) : "r"(addr));
}
__device__ __forceinline__ void mma16816(float* d, const uint32_t* a, const uint32_t* b) {
    asm volatile("mma.sync.aligned.m16n8k16.row.col.f32.bf16.bf16.f32 "
                 "{%0,%1,%2,%3}, {%4,%5,%6,%7}, {%8,%9}, {%0,%1,%2,%3};"
                 : "+f"(d[0]), "+f"(d[1]), "+f"(d[2]), "+f"(d[3])
                 : "r"(a[0]), "r"(a[1]), "r"(a[2]), "r"(a[3]), "r"(b[0]), "r"(b[1]));
}
__device__ __forceinline__ void cp16(uint32_t dst, const void* src) {
    asm volatile("cp.async.cg.shared.global [%0], [%1], 16;" :: "r"(dst), "l"(src));
}
__device__ __forceinline__ void cp_commit() {
    asm volatile("cp.async.commit_group;" ::: "memory");
}
template <int N>
__device__ __forceinline__ void cp_wait() {
    asm volatile("cp.async.wait_group %0;" :: "n"(N) : "memory");
}
__device__ __forceinline__ uint32_t pack_hi2(float a, float b) {
    __nv_bfloat162 v = __floats2bfloat162_rn(a, b);
    return *(uint32_t*)&v;
}

// ---------------------------------------------------------------------------
// Fused fp32 -> bf16 hi/lo split: x + all 4 weights in one launch.
// ---------------------------------------------------------------------------
#define NX4 (Mc * Dc / 4)
#define NW4 (DD / 4)

__global__ void __launch_bounds__(256)
split_all(const float* __restrict__ x,
          const float* __restrict__ w0, const float* __restrict__ w1,
          const float* __restrict__ w2, const float* __restrict__ w3,
          __nv_bfloat16* __restrict__ xhi, __nv_bfloat16* __restrict__ xlo,
          __nv_bfloat16* __restrict__ whi, __nv_bfloat16* __restrict__ wlo)
{
    const size_t c = (size_t)blockIdx.x * 256 + threadIdx.x;
    const float* src;
    __nv_bfloat16 *ho, *lo_;
    if (c < NX4) {
        src = x + c * 4;
        ho = xhi + c * 4; lo_ = xlo + c * 4;
    } else {
        const size_t r = c - NX4;
        const int w = (int)(r >> 18);
        const size_t l = (r & (NW4 - 1)) * 4;
        const float* ws = (w == 0) ? w0 : (w == 1) ? w1 : (w == 2) ? w2 : w3;
        src = ws + l;
        ho = whi + (size_t)w * DD + l; lo_ = wlo + (size_t)w * DD + l;
    }
    const float4 v = *(const float4*)src;
    const __nv_bfloat16 h0 = __float2bfloat16(v.x);
    const __nv_bfloat16 h1 = __float2bfloat16(v.y);
    const __nv_bfloat16 h2 = __float2bfloat16(v.z);
    const __nv_bfloat16 h3 = __float2bfloat16(v.w);
    __nv_bfloat162 ha, hb, la, lb;
    ha.x = h0; ha.y = h1; hb.x = h2; hb.y = h3;
    la.x = __float2bfloat16(v.x - __bfloat162float(h0));
    la.y = __float2bfloat16(v.y - __bfloat162float(h1));
    lb.x = __float2bfloat16(v.z - __bfloat162float(h2));
    lb.y = __float2bfloat16(v.w - __bfloat162float(h3));
    ((__nv_bfloat162*)ho)[0] = ha; ((__nv_bfloat162*)ho)[1] = hb;
    ((__nv_bfloat162*)lo_)[0] = la; ((__nv_bfloat162*)lo_)[1] = lb;
}

// ---------------------------------------------------------------------------
// GEMM: CTA tile 128x64, K-block 64, 2-stage cp.async, 96 KB -> 2 CTAs/SM.
// Warp grid 4m x 2n -> warp tile 32x32 (8 ldmatrix : 24 mma per ks-step).
// MODE 0: fp32 out. MODE 1: flat N=3072 QKV -> head-layout bf16 hi/lo.
// ---------------------------------------------------------------------------
#define RC_STAGE 49152
#define RC_SMEM  (2 * RC_STAGE)

template <int MODE>
__global__ void __launch_bounds__(256, 2)
gemm_rc(const __nv_bfloat16* __restrict__ Ahi, const __nv_bfloat16* __restrict__ Alo,
        const __nv_bfloat16* __restrict__ Wh, const __nv_bfloat16* __restrict__ Wl,
        const float* __restrict__ b0, const float* __restrict__ b1,
        const float* __restrict__ b2, float* __restrict__ C,
        __nv_bfloat16* __restrict__ qh, __nv_bfloat16* __restrict__ ql,
        __nv_bfloat16* __restrict__ kh, __nv_bfloat16* __restrict__ kl,
        __nv_bfloat16* __restrict__ vh, __nv_bfloat16* __restrict__ vl)
{
    extern __shared__ char smem[];
    const uint32_t sb = smem_u32(smem);
    const int tid = threadIdx.x;
    const int lane = tid & 31;
    const int wid = tid >> 5;
    const int m0 = blockIdx.y * 128;
    const int n0 = blockIdx.x * 64;
    const int wm = (wid & 3) * 32;       // 4 warps along m
    const int wn = (wid >> 2) * 32;      // 2 warps along n

    auto issue = [&](int kb, int bufo) {
#pragma unroll
        for (int it = 0; it < 8; it++) {
            const int idx = it * 256 + tid;
            const int tile = idx >> 10;
            const int r = (idx >> 3) & 127;
            const int ch = idx & 7;
            const uint32_t dst = sb + bufo + tile * 16384 + r * 128 +
                                 ((ch * 16) ^ ((r & 7) << 4));
            const __nv_bfloat16* src = tile ? Alo : Ahi;
            cp16(dst, src + (size_t)(m0 + r) * Dc + kb * 64 + ch * 8);
        }
#pragma unroll
        for (int it = 0; it < 4; it++) {
            const int idx = it * 256 + tid;
            const int wt = idx >> 9;
            const int r = (idx >> 3) & 63;
            const int ch = idx & 7;
            const uint32_t dst = sb + bufo + 32768 + wt * 8192 + r * 128 +
                                 ((ch * 16) ^ ((r & 7) << 4));
            const __nv_bfloat16* src = wt ? Wl : Wh;
            cp16(dst, src + (size_t)(n0 + r) * Dc + kb * 64 + ch * 8);
        }
        cp_commit();
    };

    const int g = lane >> 3;
    const int lr = lane & 7;
    int aRow[2];
    uint32_t aSw[2];
#pragma unroll
    for (int mf = 0; mf < 2; mf++) {
        aRow[mf] = wm + mf * 16 + ((g & 1) ? 8 : 0) + lr;
        aSw[mf] = (uint32_t)((aRow[mf] & 7) << 4);
    }
    const uint32_t aKext = (g >= 2) ? 16u : 0u;
    int bRow[2];
    uint32_t bSw[2];
#pragma unroll
    for (int p = 0; p < 2; p++) {
        bRow[p] = wn + p * 16 + ((g >= 2) ? 8 : 0) + lr;
        bSw[p] = (uint32_t)((bRow[p] & 7) << 4);
    }
    const uint32_t bKext = (g & 1) ? 16u : 0u;

    float acc[2][4][4];
#pragma unroll
    for (int mf = 0; mf < 2; mf++)
#pragma unroll
        for (int nf = 0; nf < 4; nf++)
#pragma unroll
            for (int q = 0; q < 4; q++) acc[mf][nf][q] = 0.0f;

    issue(0, 0);

    for (int kb = 0; kb < 16; kb++) {
        const int bufo = (kb & 1) * RC_STAGE;
        cp_wait<0>();
        __syncthreads();
        if (kb < 15) issue(kb + 1, RC_STAGE - bufo);

        const uint32_t bA = sb + bufo;
        const uint32_t bW = bA + 32768;
#pragma unroll
        for (int ks = 0; ks < 4; ks++) {
            uint32_t ah[2][4], al[2][4], bh[4][2], bl[4][2];
#pragma unroll
            for (int mf = 0; mf < 2; mf++) {
                const uint32_t off = (uint32_t)(aRow[mf] * 128) +
                                     (((uint32_t)(ks * 32) + aKext) ^ aSw[mf]);
                ldm_x4(ah[mf][0], ah[mf][1], ah[mf][2], ah[mf][3], bA + off);
                ldm_x4(al[mf][0], al[mf][1], al[mf][2], al[mf][3], bA + 16384 + off);
            }
#pragma unroll
            for (int p = 0; p < 2; p++) {
                const uint32_t off = (uint32_t)(bRow[p] * 128) +
                                     (((uint32_t)(ks * 32) + bKext) ^ bSw[p]);
                ldm_x4(bh[2 * p][0], bh[2 * p][1], bh[2 * p + 1][0], bh[2 * p + 1][1],
                       bW + off);
                ldm_x4(bl[2 * p][0], bl[2 * p][1], bl[2 * p + 1][0], bl[2 * p + 1][1],
                       bW + 8192 + off);
            }
#pragma unroll
            for (int mf = 0; mf < 2; mf++)
#pragma unroll
                for (int nf = 0; nf < 4; nf++) {
                    mma16816(acc[mf][nf], ah[mf], bh[nf]);
                    mma16816(acc[mf][nf], ah[mf], bl[nf]);
                    mma16816(acc[mf][nf], al[mf], bh[nf]);
                }
        }
    }

    const int tr = lane >> 2;
    const int tc2 = (lane & 3) * 2;

    if (MODE == 0) {
#pragma unroll
        for (int mf = 0; mf < 2; mf++)
#pragma unroll
            for (int nf = 0; nf < 4; nf++) {
                const int n = n0 + wn + nf * 8 + tc2;
                const float bb0 = b0[n], bb1 = b0[n + 1];
                const int mA = m0 + wm + mf * 16 + tr;
                const int mB = mA + 8;
                float2 vA, vB;
                vA.x = acc[mf][nf][0] + bb0; vA.y = acc[mf][nf][1] + bb1;
                vB.x = acc[mf][nf][2] + bb0; vB.y = acc[mf][nf][3] + bb1;
                *(float2*)(C + (size_t)mA * Dc + n) = vA;
                *(float2*)(C + (size_t)mB * Dc + n) = vB;
            }
    } else {
        const int w = n0 >> 10;
        const int nl0 = n0 & 1023;
        const float scl = (w == 0) ? ATTN_SCALE : 1.0f;
        const float* bias = (w == 0) ? b0 : (w == 1) ? b1 : b2;
        __nv_bfloat16* oh = (w == 0) ? qh : (w == 1) ? kh : vh;
        __nv_bfloat16* ol = (w == 0) ? ql : (w == 1) ? kl : vl;
#pragma unroll
        for (int mf = 0; mf < 2; mf++)
#pragma unroll
            for (int nf = 0; nf < 4; nf++) {
                const int n = nl0 + wn + nf * 8 + tc2;
                const float bb0 = bias[n], bb1 = bias[n + 1];
                const int mA = m0 + wm + mf * 16 + tr;
                const int mB = mA + 8;
                const float vA0 = (acc[mf][nf][0] + bb0) * scl;
                const float vA1 = (acc[mf][nf][1] + bb1) * scl;
                const float vB0 = (acc[mf][nf][2] + bb0) * scl;
                const float vB1 = (acc[mf][nf][3] + bb1) * scl;
                const int hh = n >> 6, hd = n & 63;
                const int bA = mA >> 11, tA = mA & 2047;
                const int bB = mB >> 11, tB = mB & 2047;
                const size_t oA = ((size_t)(bA * Hc + hh) * Tc + tA) * HDc + hd;
                const size_t oB = ((size_t)(bB * Hc + hh) * Tc + tB) * HDc + hd;
                __nv_bfloat162 hA = __floats2bfloat162_rn(vA0, vA1);
                __nv_bfloat162 hB = __floats2bfloat162_rn(vB0, vB1);
                __nv_bfloat162 lA, lB;
                lA.x = __float2bfloat16(vA0 - __bfloat162float(hA.x));
                lA.y = __float2bfloat16(vA1 - __bfloat162float(hA.y));
                lB.x = __float2bfloat16(vB0 - __bfloat162float(hB.x));
                lB.y = __float2bfloat16(vB1 - __bfloat162float(hB.y));
                *(__nv_bfloat162*)(oh + oA) = hA;
                *(__nv_bfloat162*)(oh + oB) = hB;
                *(__nv_bfloat162*)(ol + oA) = lA;
                *(__nv_bfloat162*)(ol + oB) = lB;
            }
    }
}

// ---------------------------------------------------------------------------
// Tensor-core causal flash attention (R10 known-good). BQ=128, BKV=64.
// 3-stage cp.async KV pipeline, one barrier per tile. smem 128 KB, 1 CTA/SM.
// ---------------------------------------------------------------------------
#define FL_SMEM (32768 + 3 * 32768)

__global__ void __launch_bounds__(256)
flash_mma(const __nv_bfloat16* __restrict__ Qh_, const __nv_bfloat16* __restrict__ Ql_,
          const __nv_bfloat16* __restrict__ Kh_, const __nv_bfloat16* __restrict__ Kl_,
          const __nv_bfloat16* __restrict__ Vh_, const __nv_bfloat16* __restrict__ Vl_,
          __nv_bfloat16* __restrict__ Yhi, __nv_bfloat16* __restrict__ Ylo)
{
    extern __shared__ char smem[];
    const uint32_t sb = smem_u32(smem);
    const int tid = threadIdx.x;
    const int lane = tid & 31;
    const int w = tid >> 5;
    const int qi = (int)(gridDim.x - 1) - (int)blockIdx.x;   // heavy tiles first
    const int q0 = qi * 128;
    const int h = blockIdx.y, b = blockIdx.z;
    const size_t base = (size_t)(b * Hc + h) * Tc * HDc;
    const __nv_bfloat16* Qh = Qh_ + base;
    const __nv_bfloat16* Ql = Ql_ + base;
    const __nv_bfloat16* Kh = Kh_ + base;
    const __nv_bfloat16* Kl = Kl_ + base;
    const __nv_bfloat16* Vh = Vh_ + base;
    const __nv_bfloat16* Vl = Vl_ + base;

    // Q tiles (Qh at 0, Ql at 16384) — own commit group
#pragma unroll
    for (int it = 0; it < 4; it++) {
        const int idx = it * 256 + tid;
        const int r = idx >> 3;
        const int ch = idx & 7;
        const uint32_t off = r * 128 + ((ch * 16) ^ ((r & 7) << 4));
        const size_t gi = (size_t)(q0 + r) * HDc + ch * 8;
        cp16(sb + off, Qh + gi);
        cp16(sb + 16384 + off, Ql + gi);
    }
    cp_commit();

    auto issueKV = [&](int t, int buf) {
        const int k0 = t * 64;
        const uint32_t so = sb + 32768 + buf * 32768;
#pragma unroll
        for (int it = 0; it < 2; it++) {
            const int idx = it * 256 + tid;
            const int r = idx >> 3;
            const int ch = idx & 7;
            const uint32_t off = r * 128 + ((ch * 16) ^ ((r & 7) << 4));
            const size_t gi = (size_t)(k0 + r) * HDc + ch * 8;
            cp16(so + off,         Kh + gi);
            cp16(so + 8192 + off,  Kl + gi);
            cp16(so + 16384 + off, Vh + gi);
            cp16(so + 24576 + off, Vl + gi);
        }
        cp_commit();
    };

    const int g = lane >> 3;
    const int lr = lane & 7;
    const int aRow = w * 16 + ((g & 1) ? 8 : 0) + lr;
    const uint32_t aSw = (uint32_t)((aRow & 7) << 4);
    const uint32_t aKext = (g >= 2) ? 16u : 0u;
    const int bRowBase = ((g >= 2) ? 8 : 0) + lr;
    const uint32_t bKext = (g & 1) ? 16u : 0u;
    const int vRow = lane & 15;
    const uint32_t vDext = (lane & 16) ? 16u : 0u;

    const int tr = lane >> 2;
    const int tc2 = (lane & 3) * 2;
    const int rowg0 = q0 + w * 16 + tr;
    const int rowg1 = rowg0 + 8;

    float mL[2] = { -INFINITY, -INFINITY };
    float lL[2] = { 0.0f, 0.0f };
    float o[8][4];
#pragma unroll
    for (int j = 0; j < 8; j++)
#pragma unroll
        for (int q = 0; q < 4; q++) o[j][q] = 0.0f;

    const int nt = q0 / 64 + 2;
    issueKV(0, 0);
    issueKV(1, 1);
    int nxt = 2;
    int nxtbuf = 2;
    int curbuf = 0;

    for (int t = 0; t < nt; t++) {
        const int k0 = t * 64;
        const int pend = nxt - 1 - t;
        if (pend) cp_wait<1>(); else cp_wait<0>();
        __syncthreads();
        if (nxt < nt) {
            issueKV(nxt, nxtbuf);
            nxt++;
            nxtbuf = (nxtbuf + 1 == 3) ? 0 : nxtbuf + 1;
        }

        if (k0 <= q0 + w * 16 + 15) {
            const uint32_t so = sb + 32768 + curbuf * 32768;
            float s[8][4];
#pragma unroll
            for (int j = 0; j < 8; j++)
#pragma unroll
                for (int q = 0; q < 4; q++) s[j][q] = 0.0f;

            // S = Q K^T (3-term)
#pragma unroll
            for (int ks = 0; ks < 4; ks++) {
                const uint32_t ka = (uint32_t)(ks * 32) + aKext;
                uint32_t qh4[4], ql4[4];
                const uint32_t qoff = (uint32_t)(aRow * 128) + (ka ^ aSw);
                ldm_x4(qh4[0], qh4[1], qh4[2], qh4[3], sb + qoff);
                ldm_x4(ql4[0], ql4[1], ql4[2], ql4[3], sb + 16384 + qoff);
#pragma unroll
                for (int p = 0; p < 4; p++) {
                    const int row = p * 16 + bRowBase;
                    const uint32_t off = (uint32_t)(row * 128) +
                        (((uint32_t)(ks * 32) + bKext) ^ ((uint32_t)((row & 7) << 4)));
                    uint32_t kh2[2][2], kl2[2][2];
                    ldm_x4(kh2[0][0], kh2[0][1], kh2[1][0], kh2[1][1], so + off);
                    ldm_x4(kl2[0][0], kl2[0][1], kl2[1][0], kl2[1][1], so + 8192 + off);
#pragma unroll
                    for (int u = 0; u < 2; u++) {
                        mma16816(s[2 * p + u], qh4, kh2[u]);
                        mma16816(s[2 * p + u], qh4, kl2[u]);
                        mma16816(s[2 * p + u], ql4, kh2[u]);
                    }
                }
            }

            // Causal mask
            if (k0 + 63 > q0 + w * 16) {
#pragma unroll
                for (int j = 0; j < 8; j++) {
                    const int c = k0 + j * 8 + tc2;
                    if (c > rowg0)     s[j][0] = -INFINITY;
                    if (c + 1 > rowg0) s[j][1] = -INFINITY;
                    if (c > rowg1)     s[j][2] = -INFINITY;
                    if (c + 1 > rowg1) s[j][3] = -INFINITY;
                }
            }

            // Online softmax
#pragma unroll
            for (int half = 0; half < 2; half++) {
                const int i0 = half * 2;
                float mx = -INFINITY;
#pragma unroll
                for (int j = 0; j < 8; j++)
                    mx = fmaxf(mx, fmaxf(s[j][i0], s[j][i0 + 1]));
                mx = fmaxf(mx, __shfl_xor_sync(0xffffffffu, mx, 1));
                mx = fmaxf(mx, __shfl_xor_sync(0xffffffffu, mx, 2));
                const float mn = fmaxf(mL[half], mx);
                const float alpha = __expf(mL[half] - mn);
                float rs = 0.0f;
#pragma unroll
                for (int j = 0; j < 8; j++) {
                    const float p0 = __expf(s[j][i0] - mn);
                    const float p1 = __expf(s[j][i0 + 1] - mn);
                    s[j][i0] = p0; s[j][i0 + 1] = p1;
                    rs += p0 + p1;
                }
                rs += __shfl_xor_sync(0xffffffffu, rs, 1);
                rs += __shfl_xor_sync(0xffffffffu, rs, 2);
                lL[half] = lL[half] * alpha + rs;
                mL[half] = mn;
#pragma unroll
                for (int j = 0; j < 8; j++) {
                    o[j][i0] *= alpha;
                    o[j][i0 + 1] *= alpha;
                }
            }

            // O += P V (3-term)
#pragma unroll
            for (int ks = 0; ks < 4; ks++) {
                const int j0 = 2 * ks, j1 = j0 + 1;
                uint32_t pha[4], pla[4];
                {
                    const float a0 = s[j0][0], a1 = s[j0][1];
                    const float a2 = s[j0][2], a3 = s[j0][3];
                    const float c0 = s[j1][0], c1 = s[j1][1];
                    const float c2 = s[j1][2], c3 = s[j1][3];
                    pha[0] = pack_hi2(a0, a1); pha[1] = pack_hi2(a2, a3);
                    pha[2] = pack_hi2(c0, c1); pha[3] = pack_hi2(c2, c3);
                    const __nv_bfloat162* hp0 = (const __nv_bfloat162*)&pha[0];
                    const __nv_bfloat162* hp1 = (const __nv_bfloat162*)&pha[1];
                    const __nv_bfloat162* hp2 = (const __nv_bfloat162*)&pha[2];
                    const __nv_bfloat162* hp3 = (const __nv_bfloat162*)&pha[3];
                    pla[0] = pack_hi2(a0 - __bfloat162float(hp0->x), a1 - __bfloat162float(hp0->y));
                    pla[1] = pack_hi2(a2 - __bfloat162float(hp1->x), a3 - __bfloat162float(hp1->y));
                    pla[2] = pack_hi2(c0 - __bfloat162float(hp2->x), c1 - __bfloat162float(hp2->y));
                    pla[3] = pack_hi2(c2 - __bfloat162float(hp3->x), c3 - __bfloat162float(hp3->y));
                }
                const int vr = ks * 16 + vRow;
                const uint32_t vsw = (uint32_t)((vr & 7) << 4);
#pragma unroll
                for (int pp = 0; pp < 4; pp++) {
                    const uint32_t dbyte = (uint32_t)(pp * 32) + vDext;
                    const uint32_t off = (uint32_t)(vr * 128) + (dbyte ^ vsw);
                    uint32_t vh2[2][2], vl2[2][2];
                    ldm_x4t(vh2[0][0], vh2[0][1], vh2[1][0], vh2[1][1], so + 16384 + off);
                    ldm_x4t(vl2[0][0], vl2[0][1], vl2[1][0], vl2[1][1], so + 24576 + off);
#pragma unroll
                    for (int u = 0; u < 2; u++) {
                        mma16816(o[2 * pp + u], pha, vh2[u]);
                        mma16816(o[2 * pp + u], pha, vl2[u]);
                        mma16816(o[2 * pp + u], pla, vh2[u]);
                    }
                }
            }
        }
        curbuf = (curbuf + 1 == 3) ? 0 : curbuf + 1;
    }

    // Epilogue: y (B,T,D) bf16 hi/lo
    const float inv0 = 1.0f / lL[0];
    const float inv1 = 1.0f / lL[1];
#pragma unroll
    for (int j = 0; j < 8; j++) {
        const int col = h * HDc + j * 8 + tc2;
        const float y00 = o[j][0] * inv0, y01 = o[j][1] * inv0;
        const float y10 = o[j][2] * inv1, y11 = o[j][3] * inv1;
        const size_t o0 = ((size_t)(b * Tc + rowg0)) * Dc + col;
        const size_t o1 = ((size_t)(b * Tc + rowg1)) * Dc + col;
        __nv_bfloat162 h0 = __floats2bfloat162_rn(y00, y01);
        __nv_bfloat162 h1 = __floats2bfloat162_rn(y10, y11);
        __nv_bfloat162 l0, l1;
        l0.x = __float2bfloat16(y00 - __bfloat162float(h0.x));
        l0.y = __float2bfloat16(y01 - __bfloat162float(h0.y));
        l1.x = __float2bfloat16(y10 - __bfloat162float(h1.x));
        l1.y = __float2bfloat16(y11 - __bfloat162float(h1.y));
        *(__nv_bfloat162*)(Yhi + o0) = h0;
        *(__nv_bfloat162*)(Yhi + o1) = h1;
        *(__nv_bfloat162*)(Ylo + o0) = l0;
        *(__nv_bfloat162*)(Ylo + o1) = l1;
    }
}

// ---------------------------------------------------------------------------
// Launch
// ---------------------------------------------------------------------------
extern "C" void kernel_launch(void* const* d_in, const int* in_sizes, int n_in,
                              void* d_out, int out_size)
{
    const float* x  = (const float*)d_in[0];
    // d_in[1]: boolean causal mask (applied analytically)
    const float* Wq = (const float*)d_in[2];
    const float* bq = (const float*)d_in[3];
    const float* Wk = (const float*)d_in[4];
    const float* bk = (const float*)d_in[5];
    const float* Wv = (const float*)d_in[6];
    const float* bv = (const float*)d_in[7];
    const float* Wo = (const float*)d_in[8];
    const float* bo = (const float*)d_in[9];
    float* out = (float*)d_out;

    __nv_bfloat16 *xhi, *xlo, *whi, *wlo, *yhi, *ylo;
    __nv_bfloat16 *qh, *ql, *kh, *kl, *vh, *vl;
    cudaGetSymbolAddress((void**)&xhi, g_xhi);
    cudaGetSymbolAddress((void**)&xlo, g_xlo);
    cudaGetSymbolAddress((void**)&whi, g_whi);
    cudaGetSymbolAddress((void**)&wlo, g_wlo);
    cudaGetSymbolAddress((void**)&yhi, g_yhi);
    cudaGetSymbolAddress((void**)&ylo, g_ylo);
    cudaGetSymbolAddress((void**)&qh,  g_qh);
    cudaGetSymbolAddress((void**)&ql,  g_ql);
    cudaGetSymbolAddress((void**)&kh,  g_kh);
    cudaGetSymbolAddress((void**)&kl,  g_kl);
    cudaGetSymbolAddress((void**)&vh,  g_vh);
    cudaGetSymbolAddress((void**)&vl,  g_vl);

    cudaFuncSetAttribute(gemm_rc<0>, cudaFuncAttributeMaxDynamicSharedMemorySize, RC_SMEM);
    cudaFuncSetAttribute(gemm_rc<1>, cudaFuncAttributeMaxDynamicSharedMemorySize, RC_SMEM);
    cudaFuncSetAttribute(flash_mma, cudaFuncAttributeMaxDynamicSharedMemorySize, FL_SMEM);

    // Fused splits: x + Wq,Wk,Wv,Wo -> bf16 hi/lo
    split_all<<<(NX4 + 4 * NW4) / 256, 256>>>(x, Wq, Wk, Wv, Wo, xhi, xlo, whi, wlo);

    // QKV as one flat N=3072 GEMM over concatenated weights
    gemm_rc<1><<<dim3(3 * Dc / 64, Mc / 128), 256, RC_SMEM>>>(
        xhi, xlo, whi, wlo, bq, bk, bv, nullptr,
        qh, ql, kh, kl, vh, vl);

    flash_mma<<<dim3(Tc / 128, Hc, Bc), 256, FL_SMEM>>>(qh, ql, kh, kl, vh, vl, yhi, ylo);

    gemm_rc<0><<<dim3(Dc / 64, Mc / 128), 256, RC_SMEM>>>(
        yhi, ylo, whi + 3 * (size_t)DD, wlo + 3 * (size_t)DD, bo, nullptr, nullptr, out,
        nullptr, nullptr, nullptr, nullptr, nullptr, nullptr);
}

// round 13
// speedup vs baseline: 1.3843x; 1.3108x over previous
#include <cuda_runtime.h>
#include <cuda_fp16.h>
#include <math.h>
#include <stdint.h>

// Problem constants
#define Bc  2
#define Tc  2048
#define Dc  1024
#define Hc  16
#define HDc 64
#define Mc  (Bc * Tc)          // 4096
#define DD  (Dc * Dc)
#define ATTN_SCALE 0.125f

// Scratch (fp16; A-operands hi-only, B-operands hi+lo)
static __device__ __align__(16) __half g_xh[Mc * Dc];
static __device__ __align__(16) __half g_wh[4][DD], g_wl[4][DD];
static __device__ __align__(16) __half g_qh[Mc * Dc];
static __device__ __align__(16) __half g_kh[Mc * Dc], g_kl[Mc * Dc];
static __device__ __align__(16) __half g_vh[Mc * Dc], g_vl[Mc * Dc];
static __device__ __align__(16) __half g_yh[Mc * Dc];

// ---------------------------------------------------------------------------
// PTX helpers — base-target-safe (mma.sync / ldmatrix / cp.async)
// ---------------------------------------------------------------------------
__device__ __forceinline__ uint32_t smem_u32(const void* p) {
    uint32_t a;
    asm("{ .reg .u64 t; cvta.to.shared.u64 t, %1; cvt.u32.u64 %0, t; }" : "=r"(a) : "l"(p));
    return a;
}
__device__ __forceinline__ void ldm_x4(uint32_t& r0, uint32_t& r1, uint32_t& r2,
                                       uint32_t& r3, uint32_t addr) {
    asm volatile("ldmatrix.sync.aligned.m8n8.x4.shared.b16 {%0,%1,%2,%3}, [%4];"
                 : "=r"(r0), "=r"(r1), "=r"(r2), "=r"(r3) : "r"(addr));
}
__device__ __forceinline__ void ldm_x4t(uint32_t& r0, uint32_t& r1, uint32_t& r2,
                                        uint32_t& r3, uint32_t addr) {
    asm volatile("ldmatrix.sync.aligned.m8n8.x4.trans.shared.b16 {%0,%1,%2,%3}, [%4];"
                 : "=r"(r0), "=r"(r1), "=r"(r2), "=r"(r3) : "r"(addr));
}
__device__ __forceinline__ void mma16816(float* d, const uint32_t* a, const uint32_t* b) {
    asm volatile("mma.sync.aligned.m16n8k16.row.col.f32.f16.f16.f32 "
                 "{%0,%1,%2,%3}, {%4,%5,%6,%7}, {%8,%9}, {%0,%1,%2,%3};"
                 : "+f"(d[0]), "+f"(d[1]), "+f"(d[2]), "+f"(d[3])
                 : "r"(a[0]), "r"(a[1]), "r"(a[2]), "r"(a[3]), "r"(b[0]), "r"(b[1]));
}
__device__ __forceinline__ void cp16(uint32_t dst, const void* src) {
    asm volatile("cp.async.cg.shared.global [%0], [%1], 16;" :: "r"(dst), "l"(src));
}
__device__ __forceinline__ void cp_commit() {
    asm volatile("cp.async.commit_group;" ::: "memory");
}
template <int N>
__device__ __forceinline__ void cp_wait() {
    asm volatile("cp.async.wait_group %0;" :: "n"(N) : "memory");
}
__device__ __forceinline__ uint32_t pack_h2(float a, float b) {
    __half2 v = __floats2half2_rn(a, b);
    return *(uint32_t*)&v;
}

// ---------------------------------------------------------------------------
// Fused fp32 -> fp16 split: x -> hi only; weights -> hi + lo.
// ---------------------------------------------------------------------------
#define NX4 (Mc * Dc / 4)
#define NW4 (DD / 4)

__global__ void __launch_bounds__(256)
split_all(const float* __restrict__ x,
          const float* __restrict__ w0, const float* __restrict__ w1,
          const float* __restrict__ w2, const float* __restrict__ w3,
          __half* __restrict__ xh, __half* __restrict__ wh, __half* __restrict__ wl)
{
    const size_t c = (size_t)blockIdx.x * 256 + threadIdx.x;
    if (c < NX4) {
        const float4 v = *(const float4*)(x + c * 4);
        __half2 a = __floats2half2_rn(v.x, v.y);
        __half2 b = __floats2half2_rn(v.z, v.w);
        ((__half2*)(xh + c * 4))[0] = a;
        ((__half2*)(xh + c * 4))[1] = b;
    } else {
        const size_t r = c - NX4;
        const int w = (int)(r >> 18);
        const size_t l = (r & (NW4 - 1)) * 4;
        const float* ws = (w == 0) ? w0 : (w == 1) ? w1 : (w == 2) ? w2 : w3;
        const float4 v = *(const float4*)(ws + l);
        __half h0 = __float2half_rn(v.x), h1 = __float2half_rn(v.y);
        __half h2 = __float2half_rn(v.z), h3 = __float2half_rn(v.w);
        __half2 ha, hb, la, lb;
        ha.x = h0; ha.y = h1; hb.x = h2; hb.y = h3;
        la.x = __float2half_rn(v.x - __half2float(h0));
        la.y = __float2half_rn(v.y - __half2float(h1));
        lb.x = __float2half_rn(v.z - __half2float(h2));
        lb.y = __float2half_rn(v.w - __half2float(h3));
        __half* ho = wh + (size_t)w * DD + l;
        __half* lo = wl + (size_t)w * DD + l;
        ((__half2*)ho)[0] = ha; ((__half2*)ho)[1] = hb;
        ((__half2*)lo)[0] = la; ((__half2*)lo)[1] = lb;
    }
}

// ---------------------------------------------------------------------------
// GEMM (fp16 2-term: acc = Ah*Wh + Ah*Wl): CTA tile 128x64, K-block 64,
// 2-stage cp.async, stage = A-hi 16K + W-hi 8K + W-lo 8K = 32 KB -> 2 CTAs/SM.
// Warp grid 4m x 2n (warp tile 32x32): 6 ldsm : 16 mma per ks-step.
// MODE 0: fp32 out + bias. MODE 1: flat N=3072 QKV -> head layout
//         (Q: hi only, scaled; K/V: hi + lo).
// ---------------------------------------------------------------------------
#define RC_STAGE 32768
#define RC_SMEM  (2 * RC_STAGE)

template <int MODE>
__global__ void __launch_bounds__(256, 2)
gemm_rc(const __half* __restrict__ Ah_, const __half* __restrict__ Wh_,
        const __half* __restrict__ Wl_,
        const float* __restrict__ b0, const float* __restrict__ b1,
        const float* __restrict__ b2, float* __restrict__ C,
        __half* __restrict__ qh, __half* __restrict__ kh, __half* __restrict__ kl,
        __half* __restrict__ vh, __half* __restrict__ vl)
{
    extern __shared__ char smem[];
    const uint32_t sb = smem_u32(smem);
    const int tid = threadIdx.x;
    const int lane = tid & 31;
    const int wid = tid >> 5;
    const int m0 = blockIdx.y * 128;
    const int n0 = blockIdx.x * 64;
    const int wm = (wid & 3) * 32;
    const int wn = (wid >> 2) * 32;

    auto issue = [&](int kb, int bufo) {
        // A-hi: 128 rows x 8 chunks = 1024
#pragma unroll
        for (int it = 0; it < 4; it++) {
            const int idx = it * 256 + tid;
            const int r = idx >> 3;
            const int ch = idx & 7;
            const uint32_t dst = sb + bufo + r * 128 + ((ch * 16) ^ ((r & 7) << 4));
            cp16(dst, Ah_ + (size_t)(m0 + r) * Dc + kb * 64 + ch * 8);
        }
        // W hi/lo: 2 x (64 rows x 8 chunks) = 1024
#pragma unroll
        for (int it = 0; it < 4; it++) {
            const int idx = it * 256 + tid;
            const int wt = idx >> 9;
            const int r = (idx >> 3) & 63;
            const int ch = idx & 7;
            const uint32_t dst = sb + bufo + 16384 + wt * 8192 + r * 128 +
                                 ((ch * 16) ^ ((r & 7) << 4));
            const __half* src = wt ? Wl_ : Wh_;
            cp16(dst, src + (size_t)(n0 + r) * Dc + kb * 64 + ch * 8);
        }
        cp_commit();
    };

    const int g = lane >> 3;
    const int lr = lane & 7;
    int aRow[2];
    uint32_t aSw[2];
#pragma unroll
    for (int mf = 0; mf < 2; mf++) {
        aRow[mf] = wm + mf * 16 + ((g & 1) ? 8 : 0) + lr;
        aSw[mf] = (uint32_t)((aRow[mf] & 7) << 4);
    }
    const uint32_t aKext = (g >= 2) ? 16u : 0u;
    int bRow[2];
    uint32_t bSw[2];
#pragma unroll
    for (int p = 0; p < 2; p++) {
        bRow[p] = wn + p * 16 + ((g >= 2) ? 8 : 0) + lr;
        bSw[p] = (uint32_t)((bRow[p] & 7) << 4);
    }
    const uint32_t bKext = (g & 1) ? 16u : 0u;

    float acc[2][4][4];
#pragma unroll
    for (int mf = 0; mf < 2; mf++)
#pragma unroll
        for (int nf = 0; nf < 4; nf++)
#pragma unroll
            for (int q = 0; q < 4; q++) acc[mf][nf][q] = 0.0f;

    issue(0, 0);

    for (int kb = 0; kb < 16; kb++) {
        const int bufo = (kb & 1) * RC_STAGE;
        cp_wait<0>();
        __syncthreads();
        if (kb < 15) issue(kb + 1, RC_STAGE - bufo);

        const uint32_t bA = sb + bufo;
        const uint32_t bWh = bA + 16384;
        const uint32_t bWl = bA + 24576;
#pragma unroll
        for (int ks = 0; ks < 4; ks++) {
            uint32_t ah[2][4], bh[4][2], bl[4][2];
#pragma unroll
            for (int mf = 0; mf < 2; mf++) {
                const uint32_t off = (uint32_t)(aRow[mf] * 128) +
                                     (((uint32_t)(ks * 32) + aKext) ^ aSw[mf]);
                ldm_x4(ah[mf][0], ah[mf][1], ah[mf][2], ah[mf][3], bA + off);
            }
#pragma unroll
            for (int p = 0; p < 2; p++) {
                const uint32_t off = (uint32_t)(bRow[p] * 128) +
                                     (((uint32_t)(ks * 32) + bKext) ^ bSw[p]);
                ldm_x4(bh[2 * p][0], bh[2 * p][1], bh[2 * p + 1][0], bh[2 * p + 1][1],
                       bWh + off);
                ldm_x4(bl[2 * p][0], bl[2 * p][1], bl[2 * p + 1][0], bl[2 * p + 1][1],
                       bWl + off);
            }
#pragma unroll
            for (int mf = 0; mf < 2; mf++)
#pragma unroll
                for (int nf = 0; nf < 4; nf++) {
                    mma16816(acc[mf][nf], ah[mf], bh[nf]);
                    mma16816(acc[mf][nf], ah[mf], bl[nf]);
                }
        }
    }

    const int tr = lane >> 2;
    const int tc2 = (lane & 3) * 2;

    if (MODE == 0) {
#pragma unroll
        for (int mf = 0; mf < 2; mf++)
#pragma unroll
            for (int nf = 0; nf < 4; nf++) {
                const int n = n0 + wn + nf * 8 + tc2;
                const float bb0 = b0[n], bb1 = b0[n + 1];
                const int mA = m0 + wm + mf * 16 + tr;
                const int mB = mA + 8;
                float2 vA, vB;
                vA.x = acc[mf][nf][0] + bb0; vA.y = acc[mf][nf][1] + bb1;
                vB.x = acc[mf][nf][2] + bb0; vB.y = acc[mf][nf][3] + bb1;
                *(float2*)(C + (size_t)mA * Dc + n) = vA;
                *(float2*)(C + (size_t)mB * Dc + n) = vB;
            }
    } else {
        const int w = n0 >> 10;
        const int nl0 = n0 & 1023;
        const float scl = (w == 0) ? ATTN_SCALE : 1.0f;
        const float* bias = (w == 0) ? b0 : (w == 1) ? b1 : b2;
#pragma unroll
        for (int mf = 0; mf < 2; mf++)
#pragma unroll
            for (int nf = 0; nf < 4; nf++) {
                const int n = nl0 + wn + nf * 8 + tc2;
                const float bb0 = bias[n], bb1 = bias[n + 1];
                const int mA = m0 + wm + mf * 16 + tr;
                const int mB = mA + 8;
                const float vA0 = (acc[mf][nf][0] + bb0) * scl;
                const float vA1 = (acc[mf][nf][1] + bb1) * scl;
                const float vB0 = (acc[mf][nf][2] + bb0) * scl;
                const float vB1 = (acc[mf][nf][3] + bb1) * scl;
                const int hh = n >> 6, hd = n & 63;
                const int bA = mA >> 11, tA = mA & 2047;
                const int bB = mB >> 11, tB = mB & 2047;
                const size_t oA = ((size_t)(bA * Hc + hh) * Tc + tA) * HDc + hd;
                const size_t oB = ((size_t)(bB * Hc + hh) * Tc + tB) * HDc + hd;
                __half2 hA = __floats2half2_rn(vA0, vA1);
                __half2 hB = __floats2half2_rn(vB0, vB1);
                if (w == 0) {
                    *(__half2*)(qh + oA) = hA;
                    *(__half2*)(qh + oB) = hB;
                } else {
                    __half* oh = (w == 1) ? kh : vh;
                    __half* ol = (w == 1) ? kl : vl;
                    __half2 lA, lB;
                    lA.x = __float2half_rn(vA0 - __half2float(hA.x));
                    lA.y = __float2half_rn(vA1 - __half2float(hA.y));
                    lB.x = __float2half_rn(vB0 - __half2float(hB.x));
                    lB.y = __float2half_rn(vB1 - __half2float(hB.y));
                    *(__half2*)(oh + oA) = hA;
                    *(__half2*)(oh + oB) = hB;
                    *(__half2*)(ol + oA) = lA;
                    *(__half2*)(ol + oB) = lB;
                }
            }
    }
}

// ---------------------------------------------------------------------------
// Flash attention (fp16 2-term: S = Qh*(Kh+Kl), O = Ph*(Vh+Vl)). BQ=128,
// BKV=64, 3-stage KV pipeline. smem: Q-hi 16K + 3 x 32K = 112 KB.
// ---------------------------------------------------------------------------
#define FL_STAGE 32768
#define FL_SMEM (16384 + 3 * FL_STAGE)

__global__ void __launch_bounds__(256)
flash_mma(const __half* __restrict__ Qh_, const __half* __restrict__ Kh_,
          const __half* __restrict__ Kl_, const __half* __restrict__ Vh_,
          const __half* __restrict__ Vl_, __half* __restrict__ Yh_)
{
    extern __shared__ char smem[];
    const uint32_t sb = smem_u32(smem);
    const int tid = threadIdx.x;
    const int lane = tid & 31;
    const int w = tid >> 5;
    const int qi = (int)(gridDim.x - 1) - (int)blockIdx.x;   // heavy tiles first
    const int q0 = qi * 128;
    const int h = blockIdx.y, b = blockIdx.z;
    const size_t base = (size_t)(b * Hc + h) * Tc * HDc;
    const __half* Qh = Qh_ + base;
    const __half* Kh = Kh_ + base;
    const __half* Kl = Kl_ + base;
    const __half* Vh = Vh_ + base;
    const __half* Vl = Vl_ + base;

    // Q-hi tile (128 x 64) — first commit group
#pragma unroll
    for (int it = 0; it < 4; it++) {
        const int idx = it * 256 + tid;
        const int r = idx >> 3;
        const int ch = idx & 7;
        const uint32_t off = r * 128 + ((ch * 16) ^ ((r & 7) << 4));
        cp16(sb + off, Qh + (size_t)(q0 + r) * HDc + ch * 8);
    }
    cp_commit();

    auto issueKV = [&](int t, int buf) {
        const int k0 = t * 64;
        const uint32_t so = sb + 16384 + buf * FL_STAGE;
#pragma unroll
        for (int it = 0; it < 2; it++) {
            const int idx = it * 256 + tid;
            const int r = idx >> 3;
            const int ch = idx & 7;
            const uint32_t off = r * 128 + ((ch * 16) ^ ((r & 7) << 4));
            const size_t gi = (size_t)(k0 + r) * HDc + ch * 8;
            cp16(so + off,         Kh + gi);
            cp16(so + 8192 + off,  Kl + gi);
            cp16(so + 16384 + off, Vh + gi);
            cp16(so + 24576 + off, Vl + gi);
        }
        cp_commit();
    };

    const int g = lane >> 3;
    const int lr = lane & 7;
    const int aRow = w * 16 + ((g & 1) ? 8 : 0) + lr;
    const uint32_t aSw = (uint32_t)((aRow & 7) << 4);
    const uint32_t aKext = (g >= 2) ? 16u : 0u;
    const int bRowBase = ((g >= 2) ? 8 : 0) + lr;
    const uint32_t bKext = (g & 1) ? 16u : 0u;
    const int vRow = lane & 15;
    const uint32_t vDext = (lane & 16) ? 16u : 0u;

    const int tr = lane >> 2;
    const int tc2 = (lane & 3) * 2;
    const int rowg0 = q0 + w * 16 + tr;
    const int rowg1 = rowg0 + 8;

    float mL[2] = { -INFINITY, -INFINITY };
    float lL[2] = { 0.0f, 0.0f };
    float o[8][4];
#pragma unroll
    for (int j = 0; j < 8; j++)
#pragma unroll
        for (int q = 0; q < 4; q++) o[j][q] = 0.0f;

    const int nt = q0 / 64 + 2;
    issueKV(0, 0);
    issueKV(1, 1);
    int nxt = 2;
    int nxtbuf = 2;
    int curbuf = 0;

    for (int t = 0; t < nt; t++) {
        const int k0 = t * 64;
        const int pend = nxt - 1 - t;
        if (pend) cp_wait<1>(); else cp_wait<0>();
        __syncthreads();
        if (nxt < nt) {
            issueKV(nxt, nxtbuf);
            nxt++;
            nxtbuf = (nxtbuf + 1 == 3) ? 0 : nxtbuf + 1;
        }

        if (k0 <= q0 + w * 16 + 15) {
            const uint32_t so = sb + 16384 + curbuf * FL_STAGE;
            float s[8][4];
#pragma unroll
            for (int j = 0; j < 8; j++)
#pragma unroll
                for (int q = 0; q < 4; q++) s[j][q] = 0.0f;

            // S = Qh (Kh + Kl)
#pragma unroll
            for (int ks = 0; ks < 4; ks++) {
                uint32_t qh4[4];
                const uint32_t qoff = (uint32_t)(aRow * 128) +
                                      (((uint32_t)(ks * 32) + aKext) ^ aSw);
                ldm_x4(qh4[0], qh4[1], qh4[2], qh4[3], sb + qoff);
#pragma unroll
                for (int p = 0; p < 4; p++) {
                    const int row = p * 16 + bRowBase;
                    const uint32_t off = (uint32_t)(row * 128) +
                        (((uint32_t)(ks * 32) + bKext) ^ ((uint32_t)((row & 7) << 4)));
                    uint32_t kh2[2][2], kl2[2][2];
                    ldm_x4(kh2[0][0], kh2[0][1], kh2[1][0], kh2[1][1], so + off);
                    ldm_x4(kl2[0][0], kl2[0][1], kl2[1][0], kl2[1][1], so + 8192 + off);
#pragma unroll
                    for (int u = 0; u < 2; u++) {
                        mma16816(s[2 * p + u], qh4, kh2[u]);
                        mma16816(s[2 * p + u], qh4, kl2[u]);
                    }
                }
            }

            // Causal mask
            if (k0 + 63 > q0 + w * 16) {
#pragma unroll
                for (int j = 0; j < 8; j++) {
                    const int c = k0 + j * 8 + tc2;
                    if (c > rowg0)     s[j][0] = -INFINITY;
                    if (c + 1 > rowg0) s[j][1] = -INFINITY;
                    if (c > rowg1)     s[j][2] = -INFINITY;
                    if (c + 1 > rowg1) s[j][3] = -INFINITY;
                }
            }

            // Online softmax
#pragma unroll
            for (int half = 0; half < 2; half++) {
                const int i0 = half * 2;
                float mx = -INFINITY;
#pragma unroll
                for (int j = 0; j < 8; j++)
                    mx = fmaxf(mx, fmaxf(s[j][i0], s[j][i0 + 1]));
                mx = fmaxf(mx, __shfl_xor_sync(0xffffffffu, mx, 1));
                mx = fmaxf(mx, __shfl_xor_sync(0xffffffffu, mx, 2));
                const float mn = fmaxf(mL[half], mx);
                const float alpha = __expf(mL[half] - mn);
                float rs = 0.0f;
#pragma unroll
                for (int j = 0; j < 8; j++) {
                    const float p0 = __expf(s[j][i0] - mn);
                    const float p1 = __expf(s[j][i0 + 1] - mn);
                    s[j][i0] = p0; s[j][i0 + 1] = p1;
                    rs += p0 + p1;
                }
                rs += __shfl_xor_sync(0xffffffffu, rs, 1);
                rs += __shfl_xor_sync(0xffffffffu, rs, 2);
                lL[half] = lL[half] * alpha + rs;
                mL[half] = mn;
#pragma unroll
                for (int j = 0; j < 8; j++) {
                    o[j][i0] *= alpha;
                    o[j][i0 + 1] *= alpha;
                }
            }

            // O += Ph (Vh + Vl)
#pragma unroll
            for (int ks = 0; ks < 4; ks++) {
                const int j0 = 2 * ks, j1 = j0 + 1;
                uint32_t pha[4];
                pha[0] = pack_h2(s[j0][0], s[j0][1]);
                pha[1] = pack_h2(s[j0][2], s[j0][3]);
                pha[2] = pack_h2(s[j1][0], s[j1][1]);
                pha[3] = pack_h2(s[j1][2], s[j1][3]);
                const int vr = ks * 16 + vRow;
                const uint32_t vsw = (uint32_t)((vr & 7) << 4);
#pragma unroll
                for (int pp = 0; pp < 4; pp++) {
                    const uint32_t dbyte = (uint32_t)(pp * 32) + vDext;
                    const uint32_t off = (uint32_t)(vr * 128) + (dbyte ^ vsw);
                    uint32_t vh2[2][2], vl2[2][2];
                    ldm_x4t(vh2[0][0], vh2[0][1], vh2[1][0], vh2[1][1], so + 16384 + off);
                    ldm_x4t(vl2[0][0], vl2[0][1], vl2[1][0], vl2[1][1], so + 24576 + off);
#pragma unroll
                    for (int u = 0; u < 2; u++) {
                        mma16816(o[2 * pp + u], pha, vh2[u]);
                        mma16816(o[2 * pp + u], pha, vl2[u]);
                    }
                }
            }
        }
        curbuf = (curbuf + 1 == 3) ? 0 : curbuf + 1;
    }

    // Epilogue: y (B,T,D) fp16 hi only
    const float inv0 = 1.0f / lL[0];
    const float inv1 = 1.0f / lL[1];
    __half* Yp = Yh_;
#pragma unroll
    for (int j = 0; j < 8; j++) {
        const int col = h * HDc + j * 8 + tc2;
        const size_t o0 = ((size_t)(b * Tc + rowg0)) * Dc + col;
        const size_t o1 = ((size_t)(b * Tc + rowg1)) * Dc + col;
        *(__half2*)(Yp + o0) = __floats2half2_rn(o[j][0] * inv0, o[j][1] * inv0);
        *(__half2*)(Yp + o1) = __floats2half2_rn(o[j][2] * inv1, o[j][3] * inv1);
    }
}

// ---------------------------------------------------------------------------
// Launch
// ---------------------------------------------------------------------------
extern "C" void kernel_launch(void* const* d_in, const int* in_sizes, int n_in,
                              void* d_out, int out_size)
{
    const float* x  = (const float*)d_in[0];
    // d_in[1]: boolean causal mask (applied analytically)
    const float* Wq = (const float*)d_in[2];
    const float* bq = (const float*)d_in[3];
    const float* Wk = (const float*)d_in[4];
    const float* bk = (const float*)d_in[5];
    const float* Wv = (const float*)d_in[6];
    const float* bv = (const float*)d_in[7];
    const float* Wo = (const float*)d_in[8];
    const float* bo = (const float*)d_in[9];
    float* out = (float*)d_out;

    __half *xh, *wh, *wl, *qh, *kh, *kl, *vh, *vl, *yh;
    cudaGetSymbolAddress((void**)&xh, g_xh);
    cudaGetSymbolAddress((void**)&wh, g_wh);
    cudaGetSymbolAddress((void**)&wl, g_wl);
    cudaGetSymbolAddress((void**)&qh, g_qh);
    cudaGetSymbolAddress((void**)&kh, g_kh);
    cudaGetSymbolAddress((void**)&kl, g_kl);
    cudaGetSymbolAddress((void**)&vh, g_vh);
    cudaGetSymbolAddress((void**)&vl, g_vl);
    cudaGetSymbolAddress((void**)&yh, g_yh);

    cudaFuncSetAttribute(gemm_rc<0>, cudaFuncAttributeMaxDynamicSharedMemorySize, RC_SMEM);
    cudaFuncSetAttribute(gemm_rc<1>, cudaFuncAttributeMaxDynamicSharedMemorySize, RC_SMEM);
    cudaFuncSetAttribute(flash_mma, cudaFuncAttributeMaxDynamicSharedMemorySize, FL_SMEM);

    // Fused splits: x -> hi; Wq,Wk,Wv,Wo -> hi + lo
    split_all<<<(NX4 + 4 * NW4) / 256, 256>>>(x, Wq, Wk, Wv, Wo, xh, wh, wl);

    // QKV as one flat N=3072 GEMM over concatenated weights
    gemm_rc<1><<<dim3(3 * Dc / 64, Mc / 128), 256, RC_SMEM>>>(
        xh, wh, wl, bq, bk, bv, nullptr, qh, kh, kl, vh, vl);

    flash_mma<<<dim3(Tc / 128, Hc, Bc), 256, FL_SMEM>>>(qh, kh, kl, vh, vl, yh);

    gemm_rc<0><<<dim3(Dc / 64, Mc / 128), 256, RC_SMEM>>>(
        yh, wh + 3 * (size_t)DD, wl + 3 * (size_t)DD, bo, nullptr, nullptr, out,
        nullptr, nullptr, nullptr, nullptr, nullptr);
}

// round 14
// speedup vs baseline: 1.4261x; 1.0302x over previous
#include <cuda_runtime.h>
#include <cuda_fp16.h>
#include <math.h>
#include <stdint.h>

// Problem constants
#define Bc  2
#define Tc  2048
#define Dc  1024
#define Hc  16
#define HDc 64
#define Mc  (Bc * Tc)          // 4096
#define DD  (Dc * Dc)
#define ATTN_SCALE 0.125f

// Scratch (fp16; A-operands hi-only, B-operands hi+lo)
static __device__ __align__(16) __half g_xh[Mc * Dc];
static __device__ __align__(16) __half g_wh[4][DD], g_wl[4][DD];
static __device__ __align__(16) __half g_qh[Mc * Dc];
static __device__ __align__(16) __half g_kh[Mc * Dc], g_kl[Mc * Dc];
static __device__ __align__(16) __half g_vh[Mc * Dc], g_vl[Mc * Dc];
static __device__ __align__(16) __half g_yh[Mc * Dc];

// ---------------------------------------------------------------------------
// PTX helpers — base-target-safe (mma.sync / ldmatrix / cp.async)
// ---------------------------------------------------------------------------
__device__ __forceinline__ uint32_t smem_u32(const void* p) {
    uint32_t a;
    asm("{ .reg .u64 t; cvta.to.shared.u64 t, %1; cvt.u32.u64 %0, t; }" : "=r"(a) : "l"(p));
    return a;
}
__device__ __forceinline__ void ldm_x4(uint32_t& r0, uint32_t& r1, uint32_t& r2,
                                       uint32_t& r3, uint32_t addr) {
    asm volatile("ldmatrix.sync.aligned.m8n8.x4.shared.b16 {%0,%1,%2,%3}, [%4];"
                 : "=r"(r0), "=r"(r1), "=r"(r2), "=r"(r3) : "r"(addr));
}
__device__ __forceinline__ void ldm_x4t(uint32_t& r0, uint32_t& r1, uint32_t& r2,
                                        uint32_t& r3, uint32_t addr) {
    asm volatile("ldmatrix.sync.aligned.m8n8.x4.trans.shared.b16 {%0,%1,%2,%3}, [%4];"
                 : "=r"(r0), "=r"(r1), "=r"(r2), "=r"(r3) : "r"(addr));
}
__device__ __forceinline__ void mma16816(float* d, const uint32_t* a, const uint32_t* b) {
    asm volatile("mma.sync.aligned.m16n8k16.row.col.f32.f16.f16.f32 "
                 "{%0,%1,%2,%3}, {%4,%5,%6,%7}, {%8,%9}, {%0,%1,%2,%3};"
                 : "+f"(d[0]), "+f"(d[1]), "+f"(d[2]), "+f"(d[3])
                 : "r"(a[0]), "r"(a[1]), "r"(a[2]), "r"(a[3]), "r"(b[0]), "r"(b[1]));
}
__device__ __forceinline__ void cp16(uint32_t dst, const void* src) {
    asm volatile("cp.async.cg.shared.global [%0], [%1], 16;" :: "r"(dst), "l"(src));
}
__device__ __forceinline__ void cp_commit() {
    asm volatile("cp.async.commit_group;" ::: "memory");
}
template <int N>
__device__ __forceinline__ void cp_wait() {
    asm volatile("cp.async.wait_group %0;" :: "n"(N) : "memory");
}
__device__ __forceinline__ uint32_t pack_h2(float a, float b) {
    __half2 v = __floats2half2_rn(a, b);
    return *(uint32_t*)&v;
}

// ---------------------------------------------------------------------------
// Fused fp32 -> fp16 split: x -> hi only; weights -> hi + lo.
// ---------------------------------------------------------------------------
#define NX4 (Mc * Dc / 4)
#define NW4 (DD / 4)

__global__ void __launch_bounds__(256)
split_all(const float* __restrict__ x,
          const float* __restrict__ w0, const float* __restrict__ w1,
          const float* __restrict__ w2, const float* __restrict__ w3,
          __half* __restrict__ xh, __half* __restrict__ wh, __half* __restrict__ wl)
{
    const size_t c = (size_t)blockIdx.x * 256 + threadIdx.x;
    if (c < NX4) {
        const float4 v = *(const float4*)(x + c * 4);
        __half2 a = __floats2half2_rn(v.x, v.y);
        __half2 b = __floats2half2_rn(v.z, v.w);
        ((__half2*)(xh + c * 4))[0] = a;
        ((__half2*)(xh + c * 4))[1] = b;
    } else {
        const size_t r = c - NX4;
        const int w = (int)(r >> 18);
        const size_t l = (r & (NW4 - 1)) * 4;
        const float* ws = (w == 0) ? w0 : (w == 1) ? w1 : (w == 2) ? w2 : w3;
        const float4 v = *(const float4*)(ws + l);
        __half h0 = __float2half_rn(v.x), h1 = __float2half_rn(v.y);
        __half h2 = __float2half_rn(v.z), h3 = __float2half_rn(v.w);
        __half2 ha, hb, la, lb;
        ha.x = h0; ha.y = h1; hb.x = h2; hb.y = h3;
        la.x = __float2half_rn(v.x - __half2float(h0));
        la.y = __float2half_rn(v.y - __half2float(h1));
        lb.x = __float2half_rn(v.z - __half2float(h2));
        lb.y = __float2half_rn(v.w - __half2float(h3));
        __half* ho = wh + (size_t)w * DD + l;
        __half* lo = wl + (size_t)w * DD + l;
        ((__half2*)ho)[0] = ha; ((__half2*)ho)[1] = hb;
        ((__half2*)lo)[0] = la; ((__half2*)lo)[1] = lb;
    }
}

// ---------------------------------------------------------------------------
// GEMM (fp16 2-term, R13 known-good): CTA tile 128x64, K-block 64,
// 2-stage cp.async, stage 32 KB -> 2 CTAs/SM. Warp grid 4m x 2n.
// MODE 0: fp32 out + bias. MODE 1: flat N=3072 QKV -> head layout.
// ---------------------------------------------------------------------------
#define RC_STAGE 32768
#define RC_SMEM  (2 * RC_STAGE)

template <int MODE>
__global__ void __launch_bounds__(256, 2)
gemm_rc(const __half* __restrict__ Ah_, const __half* __restrict__ Wh_,
        const __half* __restrict__ Wl_,
        const float* __restrict__ b0, const float* __restrict__ b1,
        const float* __restrict__ b2, float* __restrict__ C,
        __half* __restrict__ qh, __half* __restrict__ kh, __half* __restrict__ kl,
        __half* __restrict__ vh, __half* __restrict__ vl)
{
    extern __shared__ char smem[];
    const uint32_t sb = smem_u32(smem);
    const int tid = threadIdx.x;
    const int lane = tid & 31;
    const int wid = tid >> 5;
    const int m0 = blockIdx.y * 128;
    const int n0 = blockIdx.x * 64;
    const int wm = (wid & 3) * 32;
    const int wn = (wid >> 2) * 32;

    auto issue = [&](int kb, int bufo) {
#pragma unroll
        for (int it = 0; it < 4; it++) {
            const int idx = it * 256 + tid;
            const int r = idx >> 3;
            const int ch = idx & 7;
            const uint32_t dst = sb + bufo + r * 128 + ((ch * 16) ^ ((r & 7) << 4));
            cp16(dst, Ah_ + (size_t)(m0 + r) * Dc + kb * 64 + ch * 8);
        }
#pragma unroll
        for (int it = 0; it < 4; it++) {
            const int idx = it * 256 + tid;
            const int wt = idx >> 9;
            const int r = (idx >> 3) & 63;
            const int ch = idx & 7;
            const uint32_t dst = sb + bufo + 16384 + wt * 8192 + r * 128 +
                                 ((ch * 16) ^ ((r & 7) << 4));
            const __half* src = wt ? Wl_ : Wh_;
            cp16(dst, src + (size_t)(n0 + r) * Dc + kb * 64 + ch * 8);
        }
        cp_commit();
    };

    const int g = lane >> 3;
    const int lr = lane & 7;
    int aRow[2];
    uint32_t aSw[2];
#pragma unroll
    for (int mf = 0; mf < 2; mf++) {
        aRow[mf] = wm + mf * 16 + ((g & 1) ? 8 : 0) + lr;
        aSw[mf] = (uint32_t)((aRow[mf] & 7) << 4);
    }
    const uint32_t aKext = (g >= 2) ? 16u : 0u;
    int bRow[2];
    uint32_t bSw[2];
#pragma unroll
    for (int p = 0; p < 2; p++) {
        bRow[p] = wn + p * 16 + ((g >= 2) ? 8 : 0) + lr;
        bSw[p] = (uint32_t)((bRow[p] & 7) << 4);
    }
    const uint32_t bKext = (g & 1) ? 16u : 0u;

    float acc[2][4][4];
#pragma unroll
    for (int mf = 0; mf < 2; mf++)
#pragma unroll
        for (int nf = 0; nf < 4; nf++)
#pragma unroll
            for (int q = 0; q < 4; q++) acc[mf][nf][q] = 0.0f;

    issue(0, 0);

    for (int kb = 0; kb < 16; kb++) {
        const int bufo = (kb & 1) * RC_STAGE;
        cp_wait<0>();
        __syncthreads();
        if (kb < 15) issue(kb + 1, RC_STAGE - bufo);

        const uint32_t bA = sb + bufo;
        const uint32_t bWh = bA + 16384;
        const uint32_t bWl = bA + 24576;
#pragma unroll
        for (int ks = 0; ks < 4; ks++) {
            uint32_t ah[2][4], bh[4][2], bl[4][2];
#pragma unroll
            for (int mf = 0; mf < 2; mf++) {
                const uint32_t off = (uint32_t)(aRow[mf] * 128) +
                                     (((uint32_t)(ks * 32) + aKext) ^ aSw[mf]);
                ldm_x4(ah[mf][0], ah[mf][1], ah[mf][2], ah[mf][3], bA + off);
            }
#pragma unroll
            for (int p = 0; p < 2; p++) {
                const uint32_t off = (uint32_t)(bRow[p] * 128) +
                                     (((uint32_t)(ks * 32) + bKext) ^ bSw[p]);
                ldm_x4(bh[2 * p][0], bh[2 * p][1], bh[2 * p + 1][0], bh[2 * p + 1][1],
                       bWh + off);
                ldm_x4(bl[2 * p][0], bl[2 * p][1], bl[2 * p + 1][0], bl[2 * p + 1][1],
                       bWl + off);
            }
#pragma unroll
            for (int mf = 0; mf < 2; mf++)
#pragma unroll
                for (int nf = 0; nf < 4; nf++) {
                    mma16816(acc[mf][nf], ah[mf], bh[nf]);
                    mma16816(acc[mf][nf], ah[mf], bl[nf]);
                }
        }
    }

    const int tr = lane >> 2;
    const int tc2 = (lane & 3) * 2;

    if (MODE == 0) {
#pragma unroll
        for (int mf = 0; mf < 2; mf++)
#pragma unroll
            for (int nf = 0; nf < 4; nf++) {
                const int n = n0 + wn + nf * 8 + tc2;
                const float bb0 = b0[n], bb1 = b0[n + 1];
                const int mA = m0 + wm + mf * 16 + tr;
                const int mB = mA + 8;
                float2 vA, vB;
                vA.x = acc[mf][nf][0] + bb0; vA.y = acc[mf][nf][1] + bb1;
                vB.x = acc[mf][nf][2] + bb0; vB.y = acc[mf][nf][3] + bb1;
                *(float2*)(C + (size_t)mA * Dc + n) = vA;
                *(float2*)(C + (size_t)mB * Dc + n) = vB;
            }
    } else {
        const int w = n0 >> 10;
        const int nl0 = n0 & 1023;
        const float scl = (w == 0) ? ATTN_SCALE : 1.0f;
        const float* bias = (w == 0) ? b0 : (w == 1) ? b1 : b2;
#pragma unroll
        for (int mf = 0; mf < 2; mf++)
#pragma unroll
            for (int nf = 0; nf < 4; nf++) {
                const int n = nl0 + wn + nf * 8 + tc2;
                const float bb0 = bias[n], bb1 = bias[n + 1];
                const int mA = m0 + wm + mf * 16 + tr;
                const int mB = mA + 8;
                const float vA0 = (acc[mf][nf][0] + bb0) * scl;
                const float vA1 = (acc[mf][nf][1] + bb1) * scl;
                const float vB0 = (acc[mf][nf][2] + bb0) * scl;
                const float vB1 = (acc[mf][nf][3] + bb1) * scl;
                const int hh = n >> 6, hd = n & 63;
                const int bA = mA >> 11, tA = mA & 2047;
                const int bB = mB >> 11, tB = mB & 2047;
                const size_t oA = ((size_t)(bA * Hc + hh) * Tc + tA) * HDc + hd;
                const size_t oB = ((size_t)(bB * Hc + hh) * Tc + tB) * HDc + hd;
                __half2 hA = __floats2half2_rn(vA0, vA1);
                __half2 hB = __floats2half2_rn(vB0, vB1);
                if (w == 0) {
                    *(__half2*)(qh + oA) = hA;
                    *(__half2*)(qh + oB) = hB;
                } else {
                    __half* oh = (w == 1) ? kh : vh;
                    __half* ol = (w == 1) ? kl : vl;
                    __half2 lA, lB;
                    lA.x = __float2half_rn(vA0 - __half2float(hA.x));
                    lA.y = __float2half_rn(vA1 - __half2float(hA.y));
                    lB.x = __float2half_rn(vB0 - __half2float(hB.x));
                    lB.y = __float2half_rn(vB1 - __half2float(hB.y));
                    *(__half2*)(oh + oA) = hA;
                    *(__half2*)(oh + oB) = hB;
                    *(__half2*)(ol + oA) = lA;
                    *(__half2*)(ol + oB) = lB;
                }
            }
    }
}

// ---------------------------------------------------------------------------
// Flash attention (fp16 2-term). BQ=128, BKV=64. 2-stage KV pipeline:
// smem = Q-hi 16K + 2 x 32K = 80 KB -> 2 CTAs/SM (regs <= 128).
// One barrier per tile: { cp_wait<0>; sync; issue(t+1); compute }.
// ---------------------------------------------------------------------------
#define FL_STAGE 32768
#define FL_SMEM (16384 + 2 * FL_STAGE)

__global__ void __launch_bounds__(256, 2)
flash_mma(const __half* __restrict__ Qh_, const __half* __restrict__ Kh_,
          const __half* __restrict__ Kl_, const __half* __restrict__ Vh_,
          const __half* __restrict__ Vl_, __half* __restrict__ Yh_)
{
    extern __shared__ char smem[];
    const uint32_t sb = smem_u32(smem);
    const int tid = threadIdx.x;
    const int lane = tid & 31;
    const int w = tid >> 5;
    const int qi = (int)(gridDim.x - 1) - (int)blockIdx.x;   // heavy tiles first
    const int q0 = qi * 128;
    const int h = blockIdx.y, b = blockIdx.z;
    const size_t base = (size_t)(b * Hc + h) * Tc * HDc;
    const __half* Qh = Qh_ + base;
    const __half* Kh = Kh_ + base;
    const __half* Kl = Kl_ + base;
    const __half* Vh = Vh_ + base;
    const __half* Vl = Vl_ + base;

    // Q-hi tile (128 x 64) — first commit group
#pragma unroll
    for (int it = 0; it < 4; it++) {
        const int idx = it * 256 + tid;
        const int r = idx >> 3;
        const int ch = idx & 7;
        const uint32_t off = r * 128 + ((ch * 16) ^ ((r & 7) << 4));
        cp16(sb + off, Qh + (size_t)(q0 + r) * HDc + ch * 8);
    }
    cp_commit();

    auto issueKV = [&](int t) {
        const int k0 = t * 64;
        const uint32_t so = sb + 16384 + (t & 1) * FL_STAGE;
#pragma unroll
        for (int it = 0; it < 2; it++) {
            const int idx = it * 256 + tid;
            const int r = idx >> 3;
            const int ch = idx & 7;
            const uint32_t off = r * 128 + ((ch * 16) ^ ((r & 7) << 4));
            const size_t gi = (size_t)(k0 + r) * HDc + ch * 8;
            cp16(so + off,         Kh + gi);
            cp16(so + 8192 + off,  Kl + gi);
            cp16(so + 16384 + off, Vh + gi);
            cp16(so + 24576 + off, Vl + gi);
        }
        cp_commit();
    };

    const int g = lane >> 3;
    const int lr = lane & 7;
    const int aRow = w * 16 + ((g & 1) ? 8 : 0) + lr;
    const uint32_t aSw = (uint32_t)((aRow & 7) << 4);
    const uint32_t aKext = (g >= 2) ? 16u : 0u;
    const int bRowBase = ((g >= 2) ? 8 : 0) + lr;
    const uint32_t bKext = (g & 1) ? 16u : 0u;
    const int vRow = lane & 15;
    const uint32_t vDext = (lane & 16) ? 16u : 0u;

    const int tr = lane >> 2;
    const int tc2 = (lane & 3) * 2;
    const int rowg0 = q0 + w * 16 + tr;
    const int rowg1 = rowg0 + 8;

    float mL[2] = { -INFINITY, -INFINITY };
    float lL[2] = { 0.0f, 0.0f };
    float o[8][4];
#pragma unroll
    for (int j = 0; j < 8; j++)
#pragma unroll
        for (int q = 0; q < 4; q++) o[j][q] = 0.0f;

    const int nt = q0 / 64 + 2;
    issueKV(0);

    for (int t = 0; t < nt; t++) {
        const int k0 = t * 64;
        cp_wait<0>();                 // Q + all issued KV groups (incl. KV_t) landed
        __syncthreads();              // cross-warp visibility + prior reads done
        if (t + 1 < nt) issueKV(t + 1);   // targets buf (t+1)&1, read at t-1: safe

        if (k0 <= q0 + w * 16 + 15) {
            const uint32_t so = sb + 16384 + (t & 1) * FL_STAGE;
            float s[8][4];
#pragma unroll
            for (int j = 0; j < 8; j++)
#pragma unroll
                for (int q = 0; q < 4; q++) s[j][q] = 0.0f;

            // S = Qh (Kh + Kl)
#pragma unroll
            for (int ks = 0; ks < 4; ks++) {
                uint32_t qh4[4];
                const uint32_t qoff = (uint32_t)(aRow * 128) +
                                      (((uint32_t)(ks * 32) + aKext) ^ aSw);
                ldm_x4(qh4[0], qh4[1], qh4[2], qh4[3], sb + qoff);
#pragma unroll
                for (int p = 0; p < 4; p++) {
                    const int row = p * 16 + bRowBase;
                    const uint32_t off = (uint32_t)(row * 128) +
                        (((uint32_t)(ks * 32) + bKext) ^ ((uint32_t)((row & 7) << 4)));
                    uint32_t kh2[2][2], kl2[2][2];
                    ldm_x4(kh2[0][0], kh2[0][1], kh2[1][0], kh2[1][1], so + off);
                    ldm_x4(kl2[0][0], kl2[0][1], kl2[1][0], kl2[1][1], so + 8192 + off);
#pragma unroll
                    for (int u = 0; u < 2; u++) {
                        mma16816(s[2 * p + u], qh4, kh2[u]);
                        mma16816(s[2 * p + u], qh4, kl2[u]);
                    }
                }
            }

            // Causal mask
            if (k0 + 63 > q0 + w * 16) {
#pragma unroll
                for (int j = 0; j < 8; j++) {
                    const int c = k0 + j * 8 + tc2;
                    if (c > rowg0)     s[j][0] = -INFINITY;
                    if (c + 1 > rowg0) s[j][1] = -INFINITY;
                    if (c > rowg1)     s[j][2] = -INFINITY;
                    if (c + 1 > rowg1) s[j][3] = -INFINITY;
                }
            }

            // Online softmax
#pragma unroll
            for (int half = 0; half < 2; half++) {
                const int i0 = half * 2;
                float mx = -INFINITY;
#pragma unroll
                for (int j = 0; j < 8; j++)
                    mx = fmaxf(mx, fmaxf(s[j][i0], s[j][i0 + 1]));
                mx = fmaxf(mx, __shfl_xor_sync(0xffffffffu, mx, 1));
                mx = fmaxf(mx, __shfl_xor_sync(0xffffffffu, mx, 2));
                const float mn = fmaxf(mL[half], mx);
                const float alpha = __expf(mL[half] - mn);
                float rs = 0.0f;
#pragma unroll
                for (int j = 0; j < 8; j++) {
                    const float p0 = __expf(s[j][i0] - mn);
                    const float p1 = __expf(s[j][i0 + 1] - mn);
                    s[j][i0] = p0; s[j][i0 + 1] = p1;
                    rs += p0 + p1;
                }
                rs += __shfl_xor_sync(0xffffffffu, rs, 1);
                rs += __shfl_xor_sync(0xffffffffu, rs, 2);
                lL[half] = lL[half] * alpha + rs;
                mL[half] = mn;
#pragma unroll
                for (int j = 0; j < 8; j++) {
                    o[j][i0] *= alpha;
                    o[j][i0 + 1] *= alpha;
                }
            }

            // O += Ph (Vh + Vl)
#pragma unroll
            for (int ks = 0; ks < 4; ks++) {
                const int j0 = 2 * ks, j1 = j0 + 1;
                uint32_t pha[4];
                pha[0] = pack_h2(s[j0][0], s[j0][1]);
                pha[1] = pack_h2(s[j0][2], s[j0][3]);
                pha[2] = pack_h2(s[j1][0], s[j1][1]);
                pha[3] = pack_h2(s[j1][2], s[j1][3]);
                const int vr = ks * 16 + vRow;
                const uint32_t vsw = (uint32_t)((vr & 7) << 4);
#pragma unroll
                for (int pp = 0; pp < 4; pp++) {
                    const uint32_t dbyte = (uint32_t)(pp * 32) + vDext;
                    const uint32_t off = (uint32_t)(vr * 128) + (dbyte ^ vsw);
                    uint32_t vh2[2][2], vl2[2][2];
                    ldm_x4t(vh2[0][0], vh2[0][1], vh2[1][0], vh2[1][1], so + 16384 + off);
                    ldm_x4t(vl2[0][0], vl2[0][1], vl2[1][0], vl2[1][1], so + 24576 + off);
#pragma unroll
                    for (int u = 0; u < 2; u++) {
                        mma16816(o[2 * pp + u], pha, vh2[u]);
                        mma16816(o[2 * pp + u], pha, vl2[u]);
                    }
                }
            }
        }
    }

    // Epilogue: y (B,T,D) fp16 hi only
    const float inv0 = 1.0f / lL[0];
    const float inv1 = 1.0f / lL[1];
    __half* Yp = Yh_;
#pragma unroll
    for (int j = 0; j < 8; j++) {
        const int col = h * HDc + j * 8 + tc2;
        const size_t o0 = ((size_t)(b * Tc + rowg0)) * Dc + col;
        const size_t o1 = ((size_t)(b * Tc + rowg1)) * Dc + col;
        *(__half2*)(Yp + o0) = __floats2half2_rn(o[j][0] * inv0, o[j][1] * inv0);
        *(__half2*)(Yp + o1) = __floats2half2_rn(o[j][2] * inv1, o[j][3] * inv1);
    }
}

// ---------------------------------------------------------------------------
// Launch
// ---------------------------------------------------------------------------
extern "C" void kernel_launch(void* const* d_in, const int* in_sizes, int n_in,
                              void* d_out, int out_size)
{
    const float* x  = (const float*)d_in[0];
    // d_in[1]: boolean causal mask (applied analytically)
    const float* Wq = (const float*)d_in[2];
    const float* bq = (const float*)d_in[3];
    const float* Wk = (const float*)d_in[4];
    const float* bk = (const float*)d_in[5];
    const float* Wv = (const float*)d_in[6];
    const float* bv = (const float*)d_in[7];
    const float* Wo = (const float*)d_in[8];
    const float* bo = (const float*)d_in[9];
    float* out = (float*)d_out;

    __half *xh, *wh, *wl, *qh, *kh, *kl, *vh, *vl, *yh;
    cudaGetSymbolAddress((void**)&xh, g_xh);
    cudaGetSymbolAddress((void**)&wh, g_wh);
    cudaGetSymbolAddress((void**)&wl, g_wl);
    cudaGetSymbolAddress((void**)&qh, g_qh);
    cudaGetSymbolAddress((void**)&kh, g_kh);
    cudaGetSymbolAddress((void**)&kl, g_kl);
    cudaGetSymbolAddress((void**)&vh, g_vh);
    cudaGetSymbolAddress((void**)&vl, g_vl);
    cudaGetSymbolAddress((void**)&yh, g_yh);

    cudaFuncSetAttribute(gemm_rc<0>, cudaFuncAttributeMaxDynamicSharedMemorySize, RC_SMEM);
    cudaFuncSetAttribute(gemm_rc<1>, cudaFuncAttributeMaxDynamicSharedMemorySize, RC_SMEM);
    cudaFuncSetAttribute(flash_mma, cudaFuncAttributeMaxDynamicSharedMemorySize, FL_SMEM);

    // Fused splits: x -> hi; Wq,Wk,Wv,Wo -> hi + lo
    split_all<<<(NX4 + 4 * NW4) / 256, 256>>>(x, Wq, Wk, Wv, Wo, xh, wh, wl);

    // QKV as one flat N=3072 GEMM over concatenated weights
    gemm_rc<1><<<dim3(3 * Dc / 64, Mc / 128), 256, RC_SMEM>>>(
        xh, wh, wl, bq, bk, bv, nullptr, qh, kh, kl, vh, vl);

    flash_mma<<<dim3(Tc / 128, Hc, Bc), 256, FL_SMEM>>>(qh, kh, kl, vh, vl, yh);

    gemm_rc<0><<<dim3(Dc / 64, Mc / 128), 256, RC_SMEM>>>(
        yh, wh + 3 * (size_t)DD, wl + 3 * (size_t)DD, bo, nullptr, nullptr, out,
        nullptr, nullptr, nullptr, nullptr, nullptr);
}

// round 15
// speedup vs baseline: 1.4314x; 1.0037x over previous
#include <cuda_runtime.h>
#include <cuda_fp16.h>
#include <math.h>
#include <stdint.h>

// Problem constants
#define Bc  2
#define Tc  2048
#define Dc  1024
#define Hc  16
#define HDc 64
#define Mc  (Bc * Tc)          // 4096
#define DD  (Dc * Dc)
#define ATTN_SCALE 0.125f

// Scratch (fp16; A-operands hi-only, B-operands hi+lo)
static __device__ __align__(16) __half g_xh[Mc * Dc];
static __device__ __align__(16) __half g_wh[4][DD], g_wl[4][DD];
static __device__ __align__(16) __half g_qh[Mc * Dc];
static __device__ __align__(16) __half g_kh[Mc * Dc], g_kl[Mc * Dc];
static __device__ __align__(16) __half g_vh[Mc * Dc], g_vl[Mc * Dc];
static __device__ __align__(16) __half g_yh[Mc * Dc];

// ---------------------------------------------------------------------------
// PTX helpers — base-target-safe (mma.sync / ldmatrix / cp.async)
// ---------------------------------------------------------------------------
__device__ __forceinline__ uint32_t smem_u32(const void* p) {
    uint32_t a;
    asm("{ .reg .u64 t; cvta.to.shared.u64 t, %1; cvt.u32.u64 %0, t; }" : "=r"(a) : "l"(p));
    return a;
}
__device__ __forceinline__ void ldm_x4(uint32_t& r0, uint32_t& r1, uint32_t& r2,
                                       uint32_t& r3, uint32_t addr) {
    asm volatile("ldmatrix.sync.aligned.m8n8.x4.shared.b16 {%0,%1,%2,%3}, [%4];"
                 : "=r"(r0), "=r"(r1), "=r"(r2), "=r"(r3) : "r"(addr));
}
__device__ __forceinline__ void ldm_x4t(uint32_t& r0, uint32_t& r1, uint32_t& r2,
                                        uint32_t& r3, uint32_t addr) {
    asm volatile("ldmatrix.sync.aligned.m8n8.x4.trans.shared.b16 {%0,%1,%2,%3}, [%4];"
                 : "=r"(r0), "=r"(r1), "=r"(r2), "=r"(r3) : "r"(addr));
}
__device__ __forceinline__ void mma16816(float* d, const uint32_t* a, const uint32_t* b) {
    asm volatile("mma.sync.aligned.m16n8k16.row.col.f32.f16.f16.f32 "
                 "{%0,%1,%2,%3}, {%4,%5,%6,%7}, {%8,%9}, {%0,%1,%2,%3};"
                 : "+f"(d[0]), "+f"(d[1]), "+f"(d[2]), "+f"(d[3])
                 : "r"(a[0]), "r"(a[1]), "r"(a[2]), "r"(a[3]), "r"(b[0]), "r"(b[1]));
}
__device__ __forceinline__ void cp16(uint32_t dst, const void* src) {
    asm volatile("cp.async.cg.shared.global [%0], [%1], 16;" :: "r"(dst), "l"(src));
}
__device__ __forceinline__ void cp_commit() {
    asm volatile("cp.async.commit_group;" ::: "memory");
}
template <int N>
__device__ __forceinline__ void cp_wait() {
    asm volatile("cp.async.wait_group %0;" :: "n"(N) : "memory");
}
__device__ __forceinline__ uint32_t pack_h2(float a, float b) {
    __half2 v = __floats2half2_rn(a, b);
    return *(uint32_t*)&v;
}

// ---------------------------------------------------------------------------
// Fused fp32 -> fp16 split: x -> hi only; weights -> hi + lo.
// ---------------------------------------------------------------------------
#define NX4 (Mc * Dc / 4)
#define NW4 (DD / 4)

__global__ void __launch_bounds__(256)
split_all(const float* __restrict__ x,
          const float* __restrict__ w0, const float* __restrict__ w1,
          const float* __restrict__ w2, const float* __restrict__ w3,
          __half* __restrict__ xh, __half* __restrict__ wh, __half* __restrict__ wl)
{
    const size_t c = (size_t)blockIdx.x * 256 + threadIdx.x;
    if (c < NX4) {
        const float4 v = *(const float4*)(x + c * 4);
        __half2 a = __floats2half2_rn(v.x, v.y);
        __half2 b = __floats2half2_rn(v.z, v.w);
        ((__half2*)(xh + c * 4))[0] = a;
        ((__half2*)(xh + c * 4))[1] = b;
    } else {
        const size_t r = c - NX4;
        const int w = (int)(r >> 18);
        const size_t l = (r & (NW4 - 1)) * 4;
        const float* ws = (w == 0) ? w0 : (w == 1) ? w1 : (w == 2) ? w2 : w3;
        const float4 v = *(const float4*)(ws + l);
        __half h0 = __float2half_rn(v.x), h1 = __float2half_rn(v.y);
        __half h2 = __float2half_rn(v.z), h3 = __float2half_rn(v.w);
        __half2 ha, hb, la, lb;
        ha.x = h0; ha.y = h1; hb.x = h2; hb.y = h3;
        la.x = __float2half_rn(v.x - __half2float(h0));
        la.y = __float2half_rn(v.y - __half2float(h1));
        lb.x = __float2half_rn(v.z - __half2float(h2));
        lb.y = __float2half_rn(v.w - __half2float(h3));
        __half* ho = wh + (size_t)w * DD + l;
        __half* lo = wl + (size_t)w * DD + l;
        ((__half2*)ho)[0] = ha; ((__half2*)ho)[1] = hb;
        ((__half2*)lo)[0] = la; ((__half2*)lo)[1] = lb;
    }
}

// ---------------------------------------------------------------------------
// GEMM (fp16 2-term) with fragment double-buffering across ks-steps:
// load frags for ks+1 before issuing mma for ks, hiding LDSM latency.
// CTA tile 128x64, K-block 64, 2-stage cp.async, stage 32 KB -> 2 CTAs/SM.
// MODE 0: fp32 out + bias. MODE 1: flat N=3072 QKV -> head layout.
// ---------------------------------------------------------------------------
#define RC_STAGE 32768
#define RC_SMEM  (2 * RC_STAGE)

template <int MODE>
__global__ void __launch_bounds__(256, 2)
gemm_rc(const __half* __restrict__ Ah_, const __half* __restrict__ Wh_,
        const __half* __restrict__ Wl_,
        const float* __restrict__ b0, const float* __restrict__ b1,
        const float* __restrict__ b2, float* __restrict__ C,
        __half* __restrict__ qh, __half* __restrict__ kh, __half* __restrict__ kl,
        __half* __restrict__ vh, __half* __restrict__ vl)
{
    extern __shared__ char smem[];
    const uint32_t sb = smem_u32(smem);
    const int tid = threadIdx.x;
    const int lane = tid & 31;
    const int wid = tid >> 5;
    const int m0 = blockIdx.y * 128;
    const int n0 = blockIdx.x * 64;
    const int wm = (wid & 3) * 32;
    const int wn = (wid >> 2) * 32;

    auto issue = [&](int kb, int bufo) {
#pragma unroll
        for (int it = 0; it < 4; it++) {
            const int idx = it * 256 + tid;
            const int r = idx >> 3;
            const int ch = idx & 7;
            const uint32_t dst = sb + bufo + r * 128 + ((ch * 16) ^ ((r & 7) << 4));
            cp16(dst, Ah_ + (size_t)(m0 + r) * Dc + kb * 64 + ch * 8);
        }
#pragma unroll
        for (int it = 0; it < 4; it++) {
            const int idx = it * 256 + tid;
            const int wt = idx >> 9;
            const int r = (idx >> 3) & 63;
            const int ch = idx & 7;
            const uint32_t dst = sb + bufo + 16384 + wt * 8192 + r * 128 +
                                 ((ch * 16) ^ ((r & 7) << 4));
            const __half* src = wt ? Wl_ : Wh_;
            cp16(dst, src + (size_t)(n0 + r) * Dc + kb * 64 + ch * 8);
        }
        cp_commit();
    };

    const int g = lane >> 3;
    const int lr = lane & 7;
    int aRow[2];
    uint32_t aSw[2];
#pragma unroll
    for (int mf = 0; mf < 2; mf++) {
        aRow[mf] = wm + mf * 16 + ((g & 1) ? 8 : 0) + lr;
        aSw[mf] = (uint32_t)((aRow[mf] & 7) << 4);
    }
    const uint32_t aKext = (g >= 2) ? 16u : 0u;
    int bRow[2];
    uint32_t bSw[2];
#pragma unroll
    for (int p = 0; p < 2; p++) {
        bRow[p] = wn + p * 16 + ((g >= 2) ? 8 : 0) + lr;
        bSw[p] = (uint32_t)((bRow[p] & 7) << 4);
    }
    const uint32_t bKext = (g & 1) ? 16u : 0u;

    float acc[2][4][4];
#pragma unroll
    for (int mf = 0; mf < 2; mf++)
#pragma unroll
        for (int nf = 0; nf < 4; nf++)
#pragma unroll
            for (int q = 0; q < 4; q++) acc[mf][nf][q] = 0.0f;

    issue(0, 0);

    for (int kb = 0; kb < 16; kb++) {
        const int bufo = (kb & 1) * RC_STAGE;
        cp_wait<0>();
        __syncthreads();
        if (kb < 15) issue(kb + 1, RC_STAGE - bufo);

        const uint32_t bA = sb + bufo;
        const uint32_t bWh = bA + 16384;
        const uint32_t bWl = bA + 24576;

        // Double-buffered fragments across ks-steps
        uint32_t ahf[2][2][4], bhf[2][4][2], blf[2][4][2];

        auto ldfrags = [&](int ks, int bi) {
#pragma unroll
            for (int mf = 0; mf < 2; mf++) {
                const uint32_t off = (uint32_t)(aRow[mf] * 128) +
                                     (((uint32_t)(ks * 32) + aKext) ^ aSw[mf]);
                ldm_x4(ahf[bi][mf][0], ahf[bi][mf][1], ahf[bi][mf][2], ahf[bi][mf][3],
                       bA + off);
            }
#pragma unroll
            for (int p = 0; p < 2; p++) {
                const uint32_t off = (uint32_t)(bRow[p] * 128) +
                                     (((uint32_t)(ks * 32) + bKext) ^ bSw[p]);
                ldm_x4(bhf[bi][2 * p][0], bhf[bi][2 * p][1],
                       bhf[bi][2 * p + 1][0], bhf[bi][2 * p + 1][1], bWh + off);
                ldm_x4(blf[bi][2 * p][0], blf[bi][2 * p][1],
                       blf[bi][2 * p + 1][0], blf[bi][2 * p + 1][1], bWl + off);
            }
        };

        ldfrags(0, 0);
#pragma unroll
        for (int ks = 0; ks < 4; ks++) {
            const int cur = ks & 1;
            if (ks < 3) ldfrags(ks + 1, cur ^ 1);
#pragma unroll
            for (int mf = 0; mf < 2; mf++)
#pragma unroll
                for (int nf = 0; nf < 4; nf++) {
                    mma16816(acc[mf][nf], ahf[cur][mf], bhf[cur][nf]);
                    mma16816(acc[mf][nf], ahf[cur][mf], blf[cur][nf]);
                }
        }
    }

    const int tr = lane >> 2;
    const int tc2 = (lane & 3) * 2;

    if (MODE == 0) {
#pragma unroll
        for (int mf = 0; mf < 2; mf++)
#pragma unroll
            for (int nf = 0; nf < 4; nf++) {
                const int n = n0 + wn + nf * 8 + tc2;
                const float bb0 = b0[n], bb1 = b0[n + 1];
                const int mA = m0 + wm + mf * 16 + tr;
                const int mB = mA + 8;
                float2 vA, vB;
                vA.x = acc[mf][nf][0] + bb0; vA.y = acc[mf][nf][1] + bb1;
                vB.x = acc[mf][nf][2] + bb0; vB.y = acc[mf][nf][3] + bb1;
                *(float2*)(C + (size_t)mA * Dc + n) = vA;
                *(float2*)(C + (size_t)mB * Dc + n) = vB;
            }
    } else {
        const int w = n0 >> 10;
        const int nl0 = n0 & 1023;
        const float scl = (w == 0) ? ATTN_SCALE : 1.0f;
        const float* bias = (w == 0) ? b0 : (w == 1) ? b1 : b2;
#pragma unroll
        for (int mf = 0; mf < 2; mf++)
#pragma unroll
            for (int nf = 0; nf < 4; nf++) {
                const int n = nl0 + wn + nf * 8 + tc2;
                const float bb0 = bias[n], bb1 = bias[n + 1];
                const int mA = m0 + wm + mf * 16 + tr;
                const int mB = mA + 8;
                const float vA0 = (acc[mf][nf][0] + bb0) * scl;
                const float vA1 = (acc[mf][nf][1] + bb1) * scl;
                const float vB0 = (acc[mf][nf][2] + bb0) * scl;
                const float vB1 = (acc[mf][nf][3] + bb1) * scl;
                const int hh = n >> 6, hd = n & 63;
                const int bA = mA >> 11, tA = mA & 2047;
                const int bB = mB >> 11, tB = mB & 2047;
                const size_t oA = ((size_t)(bA * Hc + hh) * Tc + tA) * HDc + hd;
                const size_t oB = ((size_t)(bB * Hc + hh) * Tc + tB) * HDc + hd;
                __half2 hA = __floats2half2_rn(vA0, vA1);
                __half2 hB = __floats2half2_rn(vB0, vB1);
                if (w == 0) {
                    *(__half2*)(qh + oA) = hA;
                    *(__half2*)(qh + oB) = hB;
                } else {
                    __half* oh = (w == 1) ? kh : vh;
                    __half* ol = (w == 1) ? kl : vl;
                    __half2 lA, lB;
                    lA.x = __float2half_rn(vA0 - __half2float(hA.x));
                    lA.y = __float2half_rn(vA1 - __half2float(hA.y));
                    lB.x = __float2half_rn(vB0 - __half2float(hB.x));
                    lB.y = __float2half_rn(vB1 - __half2float(hB.y));
                    *(__half2*)(oh + oA) = hA;
                    *(__half2*)(oh + oB) = hB;
                    *(__half2*)(ol + oA) = lA;
                    *(__half2*)(ol + oB) = lB;
                }
            }
    }
}

// ---------------------------------------------------------------------------
// Flash attention (fp16 2-term, R14 known-good). BQ=128, BKV=64.
// 2-stage KV pipeline, smem 80 KB -> 2 CTAs/SM.
// ---------------------------------------------------------------------------
#define FL_STAGE 32768
#define FL_SMEM (16384 + 2 * FL_STAGE)

__global__ void __launch_bounds__(256, 2)
flash_mma(const __half* __restrict__ Qh_, const __half* __restrict__ Kh_,
          const __half* __restrict__ Kl_, const __half* __restrict__ Vh_,
          const __half* __restrict__ Vl_, __half* __restrict__ Yh_)
{
    extern __shared__ char smem[];
    const uint32_t sb = smem_u32(smem);
    const int tid = threadIdx.x;
    const int lane = tid & 31;
    const int w = tid >> 5;
    const int qi = (int)(gridDim.x - 1) - (int)blockIdx.x;   // heavy tiles first
    const int q0 = qi * 128;
    const int h = blockIdx.y, b = blockIdx.z;
    const size_t base = (size_t)(b * Hc + h) * Tc * HDc;
    const __half* Qh = Qh_ + base;
    const __half* Kh = Kh_ + base;
    const __half* Kl = Kl_ + base;
    const __half* Vh = Vh_ + base;
    const __half* Vl = Vl_ + base;

    // Q-hi tile (128 x 64) — first commit group
#pragma unroll
    for (int it = 0; it < 4; it++) {
        const int idx = it * 256 + tid;
        const int r = idx >> 3;
        const int ch = idx & 7;
        const uint32_t off = r * 128 + ((ch * 16) ^ ((r & 7) << 4));
        cp16(sb + off, Qh + (size_t)(q0 + r) * HDc + ch * 8);
    }
    cp_commit();

    auto issueKV = [&](int t) {
        const int k0 = t * 64;
        const uint32_t so = sb + 16384 + (t & 1) * FL_STAGE;
#pragma unroll
        for (int it = 0; it < 2; it++) {
            const int idx = it * 256 + tid;
            const int r = idx >> 3;
            const int ch = idx & 7;
            const uint32_t off = r * 128 + ((ch * 16) ^ ((r & 7) << 4));
            const size_t gi = (size_t)(k0 + r) * HDc + ch * 8;
            cp16(so + off,         Kh + gi);
            cp16(so + 8192 + off,  Kl + gi);
            cp16(so + 16384 + off, Vh + gi);
            cp16(so + 24576 + off, Vl + gi);
        }
        cp_commit();
    };

    const int g = lane >> 3;
    const int lr = lane & 7;
    const int aRow = w * 16 + ((g & 1) ? 8 : 0) + lr;
    const uint32_t aSw = (uint32_t)((aRow & 7) << 4);
    const uint32_t aKext = (g >= 2) ? 16u : 0u;
    const int bRowBase = ((g >= 2) ? 8 : 0) + lr;
    const uint32_t bKext = (g & 1) ? 16u : 0u;
    const int vRow = lane & 15;
    const uint32_t vDext = (lane & 16) ? 16u : 0u;

    const int tr = lane >> 2;
    const int tc2 = (lane & 3) * 2;
    const int rowg0 = q0 + w * 16 + tr;
    const int rowg1 = rowg0 + 8;

    float mL[2] = { -INFINITY, -INFINITY };
    float lL[2] = { 0.0f, 0.0f };
    float o[8][4];
#pragma unroll
    for (int j = 0; j < 8; j++)
#pragma unroll
        for (int q = 0; q < 4; q++) o[j][q] = 0.0f;

    const int nt = q0 / 64 + 2;
    issueKV(0);

    for (int t = 0; t < nt; t++) {
        const int k0 = t * 64;
        cp_wait<0>();
        __syncthreads();
        if (t + 1 < nt) issueKV(t + 1);

        if (k0 <= q0 + w * 16 + 15) {
            const uint32_t so = sb + 16384 + (t & 1) * FL_STAGE;
            float s[8][4];
#pragma unroll
            for (int j = 0; j < 8; j++)
#pragma unroll
                for (int q = 0; q < 4; q++) s[j][q] = 0.0f;

            // S = Qh (Kh + Kl)
#pragma unroll
            for (int ks = 0; ks < 4; ks++) {
                uint32_t qh4[4];
                const uint32_t qoff = (uint32_t)(aRow * 128) +
                                      (((uint32_t)(ks * 32) + aKext) ^ aSw);
                ldm_x4(qh4[0], qh4[1], qh4[2], qh4[3], sb + qoff);
#pragma unroll
                for (int p = 0; p < 4; p++) {
                    const int row = p * 16 + bRowBase;
                    const uint32_t off = (uint32_t)(row * 128) +
                        (((uint32_t)(ks * 32) + bKext) ^ ((uint32_t)((row & 7) << 4)));
                    uint32_t kh2[2][2], kl2[2][2];
                    ldm_x4(kh2[0][0], kh2[0][1], kh2[1][0], kh2[1][1], so + off);
                    ldm_x4(kl2[0][0], kl2[0][1], kl2[1][0], kl2[1][1], so + 8192 + off);
#pragma unroll
                    for (int u = 0; u < 2; u++) {
                        mma16816(s[2 * p + u], qh4, kh2[u]);
                        mma16816(s[2 * p + u], qh4, kl2[u]);
                    }
                }
            }

            // Causal mask
            if (k0 + 63 > q0 + w * 16) {
#pragma unroll
                for (int j = 0; j < 8; j++) {
                    const int c = k0 + j * 8 + tc2;
                    if (c > rowg0)     s[j][0] = -INFINITY;
                    if (c + 1 > rowg0) s[j][1] = -INFINITY;
                    if (c > rowg1)     s[j][2] = -INFINITY;
                    if (c + 1 > rowg1) s[j][3] = -INFINITY;
                }
            }

            // Online softmax
#pragma unroll
            for (int half = 0; half < 2; half++) {
                const int i0 = half * 2;
                float mx = -INFINITY;
#pragma unroll
                for (int j = 0; j < 8; j++)
                    mx = fmaxf(mx, fmaxf(s[j][i0], s[j][i0 + 1]));
                mx = fmaxf(mx, __shfl_xor_sync(0xffffffffu, mx, 1));
                mx = fmaxf(mx, __shfl_xor_sync(0xffffffffu, mx, 2));
                const float mn = fmaxf(mL[half], mx);
                const float alpha = __expf(mL[half] - mn);
                float rs = 0.0f;
#pragma unroll
                for (int j = 0; j < 8; j++) {
                    const float p0 = __expf(s[j][i0] - mn);
                    const float p1 = __expf(s[j][i0 + 1] - mn);
                    s[j][i0] = p0; s[j][i0 + 1] = p1;
                    rs += p0 + p1;
                }
                rs += __shfl_xor_sync(0xffffffffu, rs, 1);
                rs += __shfl_xor_sync(0xffffffffu, rs, 2);
                lL[half] = lL[half] * alpha + rs;
                mL[half] = mn;
#pragma unroll
                for (int j = 0; j < 8; j++) {
                    o[j][i0] *= alpha;
                    o[j][i0 + 1] *= alpha;
                }
            }

            // O += Ph (Vh + Vl)
#pragma unroll
            for (int ks = 0; ks < 4; ks++) {
                const int j0 = 2 * ks, j1 = j0 + 1;
                uint32_t pha[4];
                pha[0] = pack_h2(s[j0][0], s[j0][1]);
                pha[1] = pack_h2(s[j0][2], s[j0][3]);
                pha[2] = pack_h2(s[j1][0], s[j1][1]);
                pha[3] = pack_h2(s[j1][2], s[j1][3]);
                const int vr = ks * 16 + vRow;
                const uint32_t vsw = (uint32_t)((vr & 7) << 4);
#pragma unroll
                for (int pp = 0; pp < 4; pp++) {
                    const uint32_t dbyte = (uint32_t)(pp * 32) + vDext;
                    const uint32_t off = (uint32_t)(vr * 128) + (dbyte ^ vsw);
                    uint32_t vh2[2][2], vl2[2][2];
                    ldm_x4t(vh2[0][0], vh2[0][1], vh2[1][0], vh2[1][1], so + 16384 + off);
                    ldm_x4t(vl2[0][0], vl2[0][1], vl2[1][0], vl2[1][1], so + 24576 + off);
#pragma unroll
                    for (int u = 0; u < 2; u++) {
                        mma16816(o[2 * pp + u], pha, vh2[u]);
                        mma16816(o[2 * pp + u], pha, vl2[u]);
                    }
                }
            }
        }
    }

    // Epilogue: y (B,T,D) fp16 hi only
    const float inv0 = 1.0f / lL[0];
    const float inv1 = 1.0f / lL[1];
    __half* Yp = Yh_;
#pragma unroll
    for (int j = 0; j < 8; j++) {
        const int col = h * HDc + j * 8 + tc2;
        const size_t o0 = ((size_t)(b * Tc + rowg0)) * Dc + col;
        const size_t o1 = ((size_t)(b * Tc + rowg1)) * Dc + col;
        *(__half2*)(Yp + o0) = __floats2half2_rn(o[j][0] * inv0, o[j][1] * inv0);
        *(__half2*)(Yp + o1) = __floats2half2_rn(o[j][2] * inv1, o[j][3] * inv1);
    }
}

// ---------------------------------------------------------------------------
// Launch
// ---------------------------------------------------------------------------
extern "C" void kernel_launch(void* const* d_in, const int* in_sizes, int n_in,
                              void* d_out, int out_size)
{
    const float* x  = (const float*)d_in[0];
    // d_in[1]: boolean causal mask (applied analytically)
    const float* Wq = (const float*)d_in[2];
    const float* bq = (const float*)d_in[3];
    const float* Wk = (const float*)d_in[4];
    const float* bk = (const float*)d_in[5];
    const float* Wv = (const float*)d_in[6];
    const float* bv = (const float*)d_in[7];
    const float* Wo = (const float*)d_in[8];
    const float* bo = (const float*)d_in[9];
    float* out = (float*)d_out;

    __half *xh, *wh, *wl, *qh, *kh, *kl, *vh, *vl, *yh;
    cudaGetSymbolAddress((void**)&xh, g_xh);
    cudaGetSymbolAddress((void**)&wh, g_wh);
    cudaGetSymbolAddress((void**)&wl, g_wl);
    cudaGetSymbolAddress((void**)&qh, g_qh);
    cudaGetSymbolAddress((void**)&kh, g_kh);
    cudaGetSymbolAddress((void**)&kl, g_kl);
    cudaGetSymbolAddress((void**)&vh, g_vh);
    cudaGetSymbolAddress((void**)&vl, g_vl);
    cudaGetSymbolAddress((void**)&yh, g_yh);

    cudaFuncSetAttribute(gemm_rc<0>, cudaFuncAttributeMaxDynamicSharedMemorySize, RC_SMEM);
    cudaFuncSetAttribute(gemm_rc<1>, cudaFuncAttributeMaxDynamicSharedMemorySize, RC_SMEM);
    cudaFuncSetAttribute(flash_mma, cudaFuncAttributeMaxDynamicSharedMemorySize, FL_SMEM);

    // Fused splits: x -> hi; Wq,Wk,Wv,Wo -> hi + lo
    split_all<<<(NX4 + 4 * NW4) / 256, 256>>>(x, Wq, Wk, Wv, Wo, xh, wh, wl);

    // QKV as one flat N=3072 GEMM over concatenated weights
    gemm_rc<1><<<dim3(3 * Dc / 64, Mc / 128), 256, RC_SMEM>>>(
        xh, wh, wl, bq, bk, bv, nullptr, qh, kh, kl, vh, vl);

    flash_mma<<<dim3(Tc / 128, Hc, Bc), 256, FL_SMEM>>>(qh, kh, kl, vh, vl, yh);

    gemm_rc<0><<<dim3(Dc / 64, Mc / 128), 256, RC_SMEM>>>(
        yh, wh + 3 * (size_t)DD, wl + 3 * (size_t)DD, bo, nullptr, nullptr, out,
        nullptr, nullptr, nullptr, nullptr, nullptr);
}

// round 16
// speedup vs baseline: 1.7036x; 1.1902x over previous
#include <cuda_runtime.h>
#include <cuda_fp16.h>
#include <math.h>
#include <stdint.h>

// Problem constants
#define Bc  2
#define Tc  2048
#define Dc  1024
#define Hc  16
#define HDc 64
#define Mc  (Bc * Tc)          // 4096
#define DD  (Dc * Dc)
#define ATTN_SCALE 0.125f

// Scratch (fp16; GEMM A-side + all attention operands hi-only, weights hi+lo)
static __device__ __align__(16) __half g_xh[Mc * Dc];
static __device__ __align__(16) __half g_wh[4][DD], g_wl[4][DD];
static __device__ __align__(16) __half g_qh[Mc * Dc];
static __device__ __align__(16) __half g_kh[Mc * Dc];
static __device__ __align__(16) __half g_vh[Mc * Dc];
static __device__ __align__(16) __half g_yh[Mc * Dc];

// ---------------------------------------------------------------------------
// PTX helpers — base-target-safe (mma.sync / ldmatrix / cp.async)
// ---------------------------------------------------------------------------
__device__ __forceinline__ uint32_t smem_u32(const void* p) {
    uint32_t a;
    asm("{ .reg .u64 t; cvta.to.shared.u64 t, %1; cvt.u32.u64 %0, t; }" : "=r"(a) : "l"(p));
    return a;
}
__device__ __forceinline__ void ldm_x4(uint32_t& r0, uint32_t& r1, uint32_t& r2,
                                       uint32_t& r3, uint32_t addr) {
    asm volatile("ldmatrix.sync.aligned.m8n8.x4.shared.b16 {%0,%1,%2,%3}, [%4];"
                 : "=r"(r0), "=r"(r1), "=r"(r2), "=r"(r3) : "r"(addr));
}
__device__ __forceinline__ void ldm_x4t(uint32_t& r0, uint32_t& r1, uint32_t& r2,
                                        uint32_t& r3, uint32_t addr) {
    asm volatile("ldmatrix.sync.aligned.m8n8.x4.trans.shared.b16 {%0,%1,%2,%3}, [%4];"
                 : "=r"(r0), "=r"(r1), "=r"(r2), "=r"(r3) : "r"(addr));
}
__device__ __forceinline__ void mma16816(float* d, const uint32_t* a, const uint32_t* b) {
    asm volatile("mma.sync.aligned.m16n8k16.row.col.f32.f16.f16.f32 "
                 "{%0,%1,%2,%3}, {%4,%5,%6,%7}, {%8,%9}, {%0,%1,%2,%3};"
                 : "+f"(d[0]), "+f"(d[1]), "+f"(d[2]), "+f"(d[3])
                 : "r"(a[0]), "r"(a[1]), "r"(a[2]), "r"(a[3]), "r"(b[0]), "r"(b[1]));
}
__device__ __forceinline__ void cp16(uint32_t dst, const void* src) {
    asm volatile("cp.async.cg.shared.global [%0], [%1], 16;" :: "r"(dst), "l"(src));
}
__device__ __forceinline__ void cp_commit() {
    asm volatile("cp.async.commit_group;" ::: "memory");
}
template <int N>
__device__ __forceinline__ void cp_wait() {
    asm volatile("cp.async.wait_group %0;" :: "n"(N) : "memory");
}
__device__ __forceinline__ uint32_t pack_h2(float a, float b) {
    __half2 v = __floats2half2_rn(a, b);
    return *(uint32_t*)&v;
}

// ---------------------------------------------------------------------------
// Fused fp32 -> fp16 split: x -> hi only; weights -> hi + lo.
// ---------------------------------------------------------------------------
#define NX4 (Mc * Dc / 4)
#define NW4 (DD / 4)

__global__ void __launch_bounds__(256)
split_all(const float* __restrict__ x,
          const float* __restrict__ w0, const float* __restrict__ w1,
          const float* __restrict__ w2, const float* __restrict__ w3,
          __half* __restrict__ xh, __half* __restrict__ wh, __half* __restrict__ wl)
{
    const size_t c = (size_t)blockIdx.x * 256 + threadIdx.x;
    if (c < NX4) {
        const float4 v = *(const float4*)(x + c * 4);
        __half2 a = __floats2half2_rn(v.x, v.y);
        __half2 b = __floats2half2_rn(v.z, v.w);
        ((__half2*)(xh + c * 4))[0] = a;
        ((__half2*)(xh + c * 4))[1] = b;
    } else {
        const size_t r = c - NX4;
        const int w = (int)(r >> 18);
        const size_t l = (r & (NW4 - 1)) * 4;
        const float* ws = (w == 0) ? w0 : (w == 1) ? w1 : (w == 2) ? w2 : w3;
        const float4 v = *(const float4*)(ws + l);
        __half h0 = __float2half_rn(v.x), h1 = __float2half_rn(v.y);
        __half h2 = __float2half_rn(v.z), h3 = __float2half_rn(v.w);
        __half2 ha, hb, la, lb;
        ha.x = h0; ha.y = h1; hb.x = h2; hb.y = h3;
        la.x = __float2half_rn(v.x - __half2float(h0));
        la.y = __float2half_rn(v.y - __half2float(h1));
        lb.x = __float2half_rn(v.z - __half2float(h2));
        lb.y = __float2half_rn(v.w - __half2float(h3));
        __half* ho = wh + (size_t)w * DD + l;
        __half* lo = wl + (size_t)w * DD + l;
        ((__half2*)ho)[0] = ha; ((__half2*)ho)[1] = hb;
        ((__half2*)lo)[0] = la; ((__half2*)lo)[1] = lb;
    }
}

// ---------------------------------------------------------------------------
// GEMM (fp16 2-term, R13/R15 known-good): CTA tile 128x64, K-block 64,
// 2-stage cp.async, stage 32 KB -> 2 CTAs/SM. Warp grid 4m x 2n.
// MODE 0: fp32 out + bias. MODE 1: flat N=3072 QKV -> head layout, hi-only.
// ---------------------------------------------------------------------------
#define RC_STAGE 32768
#define RC_SMEM  (2 * RC_STAGE)

template <int MODE>
__global__ void __launch_bounds__(256, 2)
gemm_rc(const __half* __restrict__ Ah_, const __half* __restrict__ Wh_,
        const __half* __restrict__ Wl_,
        const float* __restrict__ b0, const float* __restrict__ b1,
        const float* __restrict__ b2, float* __restrict__ C,
        __half* __restrict__ qh, __half* __restrict__ kh, __half* __restrict__ vh)
{
    extern __shared__ char smem[];
    const uint32_t sb = smem_u32(smem);
    const int tid = threadIdx.x;
    const int lane = tid & 31;
    const int wid = tid >> 5;
    const int m0 = blockIdx.y * 128;
    const int n0 = blockIdx.x * 64;
    const int wm = (wid & 3) * 32;
    const int wn = (wid >> 2) * 32;

    auto issue = [&](int kb, int bufo) {
#pragma unroll
        for (int it = 0; it < 4; it++) {
            const int idx = it * 256 + tid;
            const int r = idx >> 3;
            const int ch = idx & 7;
            const uint32_t dst = sb + bufo + r * 128 + ((ch * 16) ^ ((r & 7) << 4));
            cp16(dst, Ah_ + (size_t)(m0 + r) * Dc + kb * 64 + ch * 8);
        }
#pragma unroll
        for (int it = 0; it < 4; it++) {
            const int idx = it * 256 + tid;
            const int wt = idx >> 9;
            const int r = (idx >> 3) & 63;
            const int ch = idx & 7;
            const uint32_t dst = sb + bufo + 16384 + wt * 8192 + r * 128 +
                                 ((ch * 16) ^ ((r & 7) << 4));
            const __half* src = wt ? Wl_ : Wh_;
            cp16(dst, src + (size_t)(n0 + r) * Dc + kb * 64 + ch * 8);
        }
        cp_commit();
    };

    const int g = lane >> 3;
    const int lr = lane & 7;
    int aRow[2];
    uint32_t aSw[2];
#pragma unroll
    for (int mf = 0; mf < 2; mf++) {
        aRow[mf] = wm + mf * 16 + ((g & 1) ? 8 : 0) + lr;
        aSw[mf] = (uint32_t)((aRow[mf] & 7) << 4);
    }
    const uint32_t aKext = (g >= 2) ? 16u : 0u;
    int bRow[2];
    uint32_t bSw[2];
#pragma unroll
    for (int p = 0; p < 2; p++) {
        bRow[p] = wn + p * 16 + ((g >= 2) ? 8 : 0) + lr;
        bSw[p] = (uint32_t)((bRow[p] & 7) << 4);
    }
    const uint32_t bKext = (g & 1) ? 16u : 0u;

    float acc[2][4][4];
#pragma unroll
    for (int mf = 0; mf < 2; mf++)
#pragma unroll
        for (int nf = 0; nf < 4; nf++)
#pragma unroll
            for (int q = 0; q < 4; q++) acc[mf][nf][q] = 0.0f;

    issue(0, 0);

    for (int kb = 0; kb < 16; kb++) {
        const int bufo = (kb & 1) * RC_STAGE;
        cp_wait<0>();
        __syncthreads();
        if (kb < 15) issue(kb + 1, RC_STAGE - bufo);

        const uint32_t bA = sb + bufo;
        const uint32_t bWh = bA + 16384;
        const uint32_t bWl = bA + 24576;
#pragma unroll
        for (int ks = 0; ks < 4; ks++) {
            uint32_t ah[2][4], bh[4][2], bl[4][2];
#pragma unroll
            for (int mf = 0; mf < 2; mf++) {
                const uint32_t off = (uint32_t)(aRow[mf] * 128) +
                                     (((uint32_t)(ks * 32) + aKext) ^ aSw[mf]);
                ldm_x4(ah[mf][0], ah[mf][1], ah[mf][2], ah[mf][3], bA + off);
            }
#pragma unroll
            for (int p = 0; p < 2; p++) {
                const uint32_t off = (uint32_t)(bRow[p] * 128) +
                                     (((uint32_t)(ks * 32) + bKext) ^ bSw[p]);
                ldm_x4(bh[2 * p][0], bh[2 * p][1], bh[2 * p + 1][0], bh[2 * p + 1][1],
                       bWh + off);
                ldm_x4(bl[2 * p][0], bl[2 * p][1], bl[2 * p + 1][0], bl[2 * p + 1][1],
                       bWl + off);
            }
#pragma unroll
            for (int mf = 0; mf < 2; mf++)
#pragma unroll
                for (int nf = 0; nf < 4; nf++) {
                    mma16816(acc[mf][nf], ah[mf], bh[nf]);
                    mma16816(acc[mf][nf], ah[mf], bl[nf]);
                }
        }
    }

    const int tr = lane >> 2;
    const int tc2 = (lane & 3) * 2;

    if (MODE == 0) {
#pragma unroll
        for (int mf = 0; mf < 2; mf++)
#pragma unroll
            for (int nf = 0; nf < 4; nf++) {
                const int n = n0 + wn + nf * 8 + tc2;
                const float bb0 = b0[n], bb1 = b0[n + 1];
                const int mA = m0 + wm + mf * 16 + tr;
                const int mB = mA + 8;
                float2 vA, vB;
                vA.x = acc[mf][nf][0] + bb0; vA.y = acc[mf][nf][1] + bb1;
                vB.x = acc[mf][nf][2] + bb0; vB.y = acc[mf][nf][3] + bb1;
                *(float2*)(C + (size_t)mA * Dc + n) = vA;
                *(float2*)(C + (size_t)mB * Dc + n) = vB;
            }
    } else {
        const int w = n0 >> 10;
        const int nl0 = n0 & 1023;
        const float scl = (w == 0) ? ATTN_SCALE : 1.0f;
        const float* bias = (w == 0) ? b0 : (w == 1) ? b1 : b2;
        __half* oh = (w == 0) ? qh : (w == 1) ? kh : vh;
#pragma unroll
        for (int mf = 0; mf < 2; mf++)
#pragma unroll
            for (int nf = 0; nf < 4; nf++) {
                const int n = nl0 + wn + nf * 8 + tc2;
                const float bb0 = bias[n], bb1 = bias[n + 1];
                const int mA = m0 + wm + mf * 16 + tr;
                const int mB = mA + 8;
                const float vA0 = (acc[mf][nf][0] + bb0) * scl;
                const float vA1 = (acc[mf][nf][1] + bb1) * scl;
                const float vB0 = (acc[mf][nf][2] + bb0) * scl;
                const float vB1 = (acc[mf][nf][3] + bb1) * scl;
                const int hh = n >> 6, hd = n & 63;
                const int bA = mA >> 11, tA = mA & 2047;
                const int bB = mB >> 11, tB = mB & 2047;
                const size_t oA = ((size_t)(bA * Hc + hh) * Tc + tA) * HDc + hd;
                const size_t oB = ((size_t)(bB * Hc + hh) * Tc + tB) * HDc + hd;
                *(__half2*)(oh + oA) = __floats2half2_rn(vA0, vA1);
                *(__half2*)(oh + oB) = __floats2half2_rn(vB0, vB1);
            }
    }
}

// ---------------------------------------------------------------------------
// Flash attention (fp16 1-term: S = Qh*Kh, O = Ph*Vh). BQ=128, BKV=64.
// 2-stage KV pipeline; smem = Q 16K + 2 x (Kh 8K + Vh 8K) = 48 KB; 2 CTAs/SM.
// ---------------------------------------------------------------------------
#define FL_STAGE 16384
#define FL_SMEM (16384 + 2 * FL_STAGE)

__global__ void __launch_bounds__(256, 2)
flash_mma(const __half* __restrict__ Qh_, const __half* __restrict__ Kh_,
          const __half* __restrict__ Vh_, __half* __restrict__ Yh_)
{
    extern __shared__ char smem[];
    const uint32_t sb = smem_u32(smem);
    const int tid = threadIdx.x;
    const int lane = tid & 31;
    const int w = tid >> 5;
    const int qi = (int)(gridDim.x - 1) - (int)blockIdx.x;   // heavy tiles first
    const int q0 = qi * 128;
    const int h = blockIdx.y, b = blockIdx.z;
    const size_t base = (size_t)(b * Hc + h) * Tc * HDc;
    const __half* Qh = Qh_ + base;
    const __half* Kh = Kh_ + base;
    const __half* Vh = Vh_ + base;

    // Q tile (128 x 64) — first commit group
#pragma unroll
    for (int it = 0; it < 4; it++) {
        const int idx = it * 256 + tid;
        const int r = idx >> 3;
        const int ch = idx & 7;
        const uint32_t off = r * 128 + ((ch * 16) ^ ((r & 7) << 4));
        cp16(sb + off, Qh + (size_t)(q0 + r) * HDc + ch * 8);
    }
    cp_commit();

    auto issueKV = [&](int t) {
        const int k0 = t * 64;
        const uint32_t so = sb + 16384 + (t & 1) * FL_STAGE;
        // Kh (64x64) + Vh (64x64): 1024 chunks of 16 B
#pragma unroll
        for (int it = 0; it < 2; it++) {
            const int idx = it * 256 + tid;
            const int r = idx >> 3;
            const int ch = idx & 7;
            const uint32_t off = r * 128 + ((ch * 16) ^ ((r & 7) << 4));
            const size_t gi = (size_t)(k0 + r) * HDc + ch * 8;
            cp16(so + off,        Kh + gi);
            cp16(so + 8192 + off, Vh + gi);
        }
        cp_commit();
    };

    const int g = lane >> 3;
    const int lr = lane & 7;
    const int aRow = w * 16 + ((g & 1) ? 8 : 0) + lr;
    const uint32_t aSw = (uint32_t)((aRow & 7) << 4);
    const uint32_t aKext = (g >= 2) ? 16u : 0u;
    const int bRowBase = ((g >= 2) ? 8 : 0) + lr;
    const uint32_t bKext = (g & 1) ? 16u : 0u;
    const int vRow = lane & 15;
    const uint32_t vDext = (lane & 16) ? 16u : 0u;

    const int tr = lane >> 2;
    const int tc2 = (lane & 3) * 2;
    const int rowg0 = q0 + w * 16 + tr;
    const int rowg1 = rowg0 + 8;

    float mL[2] = { -INFINITY, -INFINITY };
    float lL[2] = { 0.0f, 0.0f };
    float o[8][4];
#pragma unroll
    for (int j = 0; j < 8; j++)
#pragma unroll
        for (int q = 0; q < 4; q++) o[j][q] = 0.0f;

    const int nt = q0 / 64 + 2;
    issueKV(0);

    for (int t = 0; t < nt; t++) {
        const int k0 = t * 64;
        cp_wait<0>();
        __syncthreads();
        if (t + 1 < nt) issueKV(t + 1);

        if (k0 <= q0 + w * 16 + 15) {
            const uint32_t so = sb + 16384 + (t & 1) * FL_STAGE;
            float s[8][4];
#pragma unroll
            for (int j = 0; j < 8; j++)
#pragma unroll
                for (int q = 0; q < 4; q++) s[j][q] = 0.0f;

            // S = Qh Kh^T
#pragma unroll
            for (int ks = 0; ks < 4; ks++) {
                uint32_t qh4[4];
                const uint32_t qoff = (uint32_t)(aRow * 128) +
                                      (((uint32_t)(ks * 32) + aKext) ^ aSw);
                ldm_x4(qh4[0], qh4[1], qh4[2], qh4[3], sb + qoff);
#pragma unroll
                for (int p = 0; p < 4; p++) {
                    const int row = p * 16 + bRowBase;
                    const uint32_t off = (uint32_t)(row * 128) +
                        (((uint32_t)(ks * 32) + bKext) ^ ((uint32_t)((row & 7) << 4)));
                    uint32_t kh2[2][2];
                    ldm_x4(kh2[0][0], kh2[0][1], kh2[1][0], kh2[1][1], so + off);
#pragma unroll
                    for (int u = 0; u < 2; u++)
                        mma16816(s[2 * p + u], qh4, kh2[u]);
                }
            }

            // Causal mask
            if (k0 + 63 > q0 + w * 16) {
#pragma unroll
                for (int j = 0; j < 8; j++) {
                    const int c = k0 + j * 8 + tc2;
                    if (c > rowg0)     s[j][0] = -INFINITY;
                    if (c + 1 > rowg0) s[j][1] = -INFINITY;
                    if (c > rowg1)     s[j][2] = -INFINITY;
                    if (c + 1 > rowg1) s[j][3] = -INFINITY;
                }
            }

            // Online softmax
#pragma unroll
            for (int half = 0; half < 2; half++) {
                const int i0 = half * 2;
                float mx = -INFINITY;
#pragma unroll
                for (int j = 0; j < 8; j++)
                    mx = fmaxf(mx, fmaxf(s[j][i0], s[j][i0 + 1]));
                mx = fmaxf(mx, __shfl_xor_sync(0xffffffffu, mx, 1));
                mx = fmaxf(mx, __shfl_xor_sync(0xffffffffu, mx, 2));
                const float mn = fmaxf(mL[half], mx);
                const float alpha = __expf(mL[half] - mn);
                float rs = 0.0f;
#pragma unroll
                for (int j = 0; j < 8; j++) {
                    const float p0 = __expf(s[j][i0] - mn);
                    const float p1 = __expf(s[j][i0 + 1] - mn);
                    s[j][i0] = p0; s[j][i0 + 1] = p1;
                    rs += p0 + p1;
                }
                rs += __shfl_xor_sync(0xffffffffu, rs, 1);
                rs += __shfl_xor_sync(0xffffffffu, rs, 2);
                lL[half] = lL[half] * alpha + rs;
                mL[half] = mn;
#pragma unroll
                for (int j = 0; j < 8; j++) {
                    o[j][i0] *= alpha;
                    o[j][i0 + 1] *= alpha;
                }
            }

            // O += Ph Vh
#pragma unroll
            for (int ks = 0; ks < 4; ks++) {
                const int j0 = 2 * ks, j1 = j0 + 1;
                uint32_t pha[4];
                pha[0] = pack_h2(s[j0][0], s[j0][1]);
                pha[1] = pack_h2(s[j0][2], s[j0][3]);
                pha[2] = pack_h2(s[j1][0], s[j1][1]);
                pha[3] = pack_h2(s[j1][2], s[j1][3]);
                const int vr = ks * 16 + vRow;
                const uint32_t vsw = (uint32_t)((vr & 7) << 4);
#pragma unroll
                for (int pp = 0; pp < 4; pp++) {
                    const uint32_t dbyte = (uint32_t)(pp * 32) + vDext;
                    const uint32_t off = (uint32_t)(vr * 128) + (dbyte ^ vsw);
                    uint32_t vh2[2][2];
                    ldm_x4t(vh2[0][0], vh2[0][1], vh2[1][0], vh2[1][1], so + 8192 + off);
#pragma unroll
                    for (int u = 0; u < 2; u++)
                        mma16816(o[2 * pp + u], pha, vh2[u]);
                }
            }
        }
    }

    // Epilogue: y (B,T,D) fp16 hi only
    const float inv0 = 1.0f / lL[0];
    const float inv1 = 1.0f / lL[1];
#pragma unroll
    for (int j = 0; j < 8; j++) {
        const int col = h * HDc + j * 8 + tc2;
        const size_t o0 = ((size_t)(b * Tc + rowg0)) * Dc + col;
        const size_t o1 = ((size_t)(b * Tc + rowg1)) * Dc + col;
        *(__half2*)(Yh_ + o0) = __floats2half2_rn(o[j][0] * inv0, o[j][1] * inv0);
        *(__half2*)(Yh_ + o1) = __floats2half2_rn(o[j][2] * inv1, o[j][3] * inv1);
    }
}

// ---------------------------------------------------------------------------
// Launch
// ---------------------------------------------------------------------------
extern "C" void kernel_launch(void* const* d_in, const int* in_sizes, int n_in,
                              void* d_out, int out_size)
{
    const float* x  = (const float*)d_in[0];
    // d_in[1]: boolean causal mask (applied analytically)
    const float* Wq = (const float*)d_in[2];
    const float* bq = (const float*)d_in[3];
    const float* Wk = (const float*)d_in[4];
    const float* bk = (const float*)d_in[5];
    const float* Wv = (const float*)d_in[6];
    const float* bv = (const float*)d_in[7];
    const float* Wo = (const float*)d_in[8];
    const float* bo = (const float*)d_in[9];
    float* out = (float*)d_out;

    __half *xh, *wh, *wl, *qh, *kh, *vh, *yh;
    cudaGetSymbolAddress((void**)&xh, g_xh);
    cudaGetSymbolAddress((void**)&wh, g_wh);
    cudaGetSymbolAddress((void**)&wl, g_wl);
    cudaGetSymbolAddress((void**)&qh, g_qh);
    cudaGetSymbolAddress((void**)&kh, g_kh);
    cudaGetSymbolAddress((void**)&vh, g_vh);
    cudaGetSymbolAddress((void**)&yh, g_yh);

    cudaFuncSetAttribute(gemm_rc<0>, cudaFuncAttributeMaxDynamicSharedMemorySize, RC_SMEM);
    cudaFuncSetAttribute(gemm_rc<1>, cudaFuncAttributeMaxDynamicSharedMemorySize, RC_SMEM);
    cudaFuncSetAttribute(flash_mma, cudaFuncAttributeMaxDynamicSharedMemorySize, FL_SMEM);

    // Fused splits: x -> hi; Wq,Wk,Wv,Wo -> hi + lo
    split_all<<<(NX4 + 4 * NW4) / 256, 256>>>(x, Wq, Wk, Wv, Wo, xh, wh, wl);

    // QKV as one flat N=3072 GEMM over concatenated weights (hi-only outputs)
    gemm_rc<1><<<dim3(3 * Dc / 64, Mc / 128), 256, RC_SMEM>>>(
        xh, wh, wl, bq, bk, bv, nullptr, qh, kh, vh);

    flash_mma<<<dim3(Tc / 128, Hc, Bc), 256, FL_SMEM>>>(qh, kh, vh, yh);

    gemm_rc<0><<<dim3(Dc / 64, Mc / 128), 256, RC_SMEM>>>(
        yh, wh + 3 * (size_t)DD, wl + 3 * (size_t)DD, bo, nullptr, nullptr, out,
        nullptr, nullptr, nullptr);
}

// round 17
// speedup vs baseline: 2.2316x; 1.3099x over previous
#include <cuda_runtime.h>
#include <cuda_fp16.h>
#include <math.h>
#include <stdint.h>

// Problem constants
#define Bc  2
#define Tc  2048
#define Dc  1024
#define Hc  16
#define HDc 64
#define Mc  (Bc * Tc)          // 4096
#define DD  (Dc * Dc)
#define ATTN_SCALE 0.125f

// Scratch (fp16 hi-only everywhere)
static __device__ __align__(16) __half g_xh[Mc * Dc];
static __device__ __align__(16) __half g_wh[4][DD];
static __device__ __align__(16) __half g_qh[Mc * Dc];
static __device__ __align__(16) __half g_kh[Mc * Dc];
static __device__ __align__(16) __half g_vh[Mc * Dc];
static __device__ __align__(16) __half g_yh[Mc * Dc];

// ---------------------------------------------------------------------------
// PTX helpers — base-target-safe (mma.sync / ldmatrix / cp.async)
// ---------------------------------------------------------------------------
__device__ __forceinline__ uint32_t smem_u32(const void* p) {
    uint32_t a;
    asm("{ .reg .u64 t; cvta.to.shared.u64 t, %1; cvt.u32.u64 %0, t; }" : "=r"(a) : "l"(p));
    return a;
}
__device__ __forceinline__ void ldm_x4(uint32_t& r0, uint32_t& r1, uint32_t& r2,
                                       uint32_t& r3, uint32_t addr) {
    asm volatile("ldmatrix.sync.aligned.m8n8.x4.shared.b16 {%0,%1,%2,%3}, [%4];"
                 : "=r"(r0), "=r"(r1), "=r"(r2), "=r"(r3) : "r"(addr));
}
__device__ __forceinline__ void ldm_x4t(uint32_t& r0, uint32_t& r1, uint32_t& r2,
                                        uint32_t& r3, uint32_t addr) {
    asm volatile("ldmatrix.sync.aligned.m8n8.x4.trans.shared.b16 {%0,%1,%2,%3}, [%4];"
                 : "=r"(r0), "=r"(r1), "=r"(r2), "=r"(r3) : "r"(addr));
}
__device__ __forceinline__ void mma16816(float* d, const uint32_t* a, const uint32_t* b) {
    asm volatile("mma.sync.aligned.m16n8k16.row.col.f32.f16.f16.f32 "
                 "{%0,%1,%2,%3}, {%4,%5,%6,%7}, {%8,%9}, {%0,%1,%2,%3};"
                 : "+f"(d[0]), "+f"(d[1]), "+f"(d[2]), "+f"(d[3])
                 : "r"(a[0]), "r"(a[1]), "r"(a[2]), "r"(a[3]), "r"(b[0]), "r"(b[1]));
}
__device__ __forceinline__ void cp16(uint32_t dst, const void* src) {
    asm volatile("cp.async.cg.shared.global [%0], [%1], 16;" :: "r"(dst), "l"(src));
}
__device__ __forceinline__ void cp_commit() {
    asm volatile("cp.async.commit_group;" ::: "memory");
}
template <int N>
__device__ __forceinline__ void cp_wait() {
    asm volatile("cp.async.wait_group %0;" :: "n"(N) : "memory");
}
__device__ __forceinline__ uint32_t pack_h2(float a, float b) {
    __half2 v = __floats2half2_rn(a, b);
    return *(uint32_t*)&v;
}

// ---------------------------------------------------------------------------
// Fused fp32 -> fp16 conversion: x + all 4 weights, hi only.
// ---------------------------------------------------------------------------
#define NX4 (Mc * Dc / 4)
#define NW4 (DD / 4)

__global__ void __launch_bounds__(256)
split_all(const float* __restrict__ x,
          const float* __restrict__ w0, const float* __restrict__ w1,
          const float* __restrict__ w2, const float* __restrict__ w3,
          __half* __restrict__ xh, __half* __restrict__ wh)
{
    const size_t c = (size_t)blockIdx.x * 256 + threadIdx.x;
    const float* src;
    __half* dst;
    if (c < NX4) {
        src = x + c * 4;
        dst = xh + c * 4;
    } else {
        const size_t r = c - NX4;
        const int w = (int)(r >> 18);
        const size_t l = (r & (NW4 - 1)) * 4;
        const float* ws = (w == 0) ? w0 : (w == 1) ? w1 : (w == 2) ? w2 : w3;
        src = ws + l;
        dst = wh + (size_t)w * DD + l;
    }
    const float4 v = *(const float4*)src;
    ((__half2*)dst)[0] = __floats2half2_rn(v.x, v.y);
    ((__half2*)dst)[1] = __floats2half2_rn(v.z, v.w);
}

// ---------------------------------------------------------------------------
// GEMM (fp16 1-term): CTA tile 128x64, K-block 64, 2-stage cp.async,
// stage = A 16K + W 8K = 24 KB -> 48 KB total -> 2 CTAs/SM. Warp grid 4m x 2n.
// MODE 0: fp32 out + bias. MODE 1: flat N=3072 QKV -> head layout, hi-only.
// ---------------------------------------------------------------------------
#define RC_STAGE 24576
#define RC_SMEM  (2 * RC_STAGE)

template <int MODE>
__global__ void __launch_bounds__(256, 2)
gemm_rc(const __half* __restrict__ Ah_, const __half* __restrict__ Wh_,
        const float* __restrict__ b0, const float* __restrict__ b1,
        const float* __restrict__ b2, float* __restrict__ C,
        __half* __restrict__ qh, __half* __restrict__ kh, __half* __restrict__ vh)
{
    extern __shared__ char smem[];
    const uint32_t sb = smem_u32(smem);
    const int tid = threadIdx.x;
    const int lane = tid & 31;
    const int wid = tid >> 5;
    const int m0 = blockIdx.y * 128;
    const int n0 = blockIdx.x * 64;
    const int wm = (wid & 3) * 32;
    const int wn = (wid >> 2) * 32;

    auto issue = [&](int kb, int bufo) {
        // A: 128 rows x 8 chunks = 1024
#pragma unroll
        for (int it = 0; it < 4; it++) {
            const int idx = it * 256 + tid;
            const int r = idx >> 3;
            const int ch = idx & 7;
            const uint32_t dst = sb + bufo + r * 128 + ((ch * 16) ^ ((r & 7) << 4));
            cp16(dst, Ah_ + (size_t)(m0 + r) * Dc + kb * 64 + ch * 8);
        }
        // W: 64 rows x 8 chunks = 512
#pragma unroll
        for (int it = 0; it < 2; it++) {
            const int idx = it * 256 + tid;
            const int r = idx >> 3;
            const int ch = idx & 7;
            const uint32_t dst = sb + bufo + 16384 + r * 128 +
                                 ((ch * 16) ^ ((r & 7) << 4));
            cp16(dst, Wh_ + (size_t)(n0 + r) * Dc + kb * 64 + ch * 8);
        }
        cp_commit();
    };

    const int g = lane >> 3;
    const int lr = lane & 7;
    int aRow[2];
    uint32_t aSw[2];
#pragma unroll
    for (int mf = 0; mf < 2; mf++) {
        aRow[mf] = wm + mf * 16 + ((g & 1) ? 8 : 0) + lr;
        aSw[mf] = (uint32_t)((aRow[mf] & 7) << 4);
    }
    const uint32_t aKext = (g >= 2) ? 16u : 0u;
    int bRow[2];
    uint32_t bSw[2];
#pragma unroll
    for (int p = 0; p < 2; p++) {
        bRow[p] = wn + p * 16 + ((g >= 2) ? 8 : 0) + lr;
        bSw[p] = (uint32_t)((bRow[p] & 7) << 4);
    }
    const uint32_t bKext = (g & 1) ? 16u : 0u;

    float acc[2][4][4];
#pragma unroll
    for (int mf = 0; mf < 2; mf++)
#pragma unroll
        for (int nf = 0; nf < 4; nf++)
#pragma unroll
            for (int q = 0; q < 4; q++) acc[mf][nf][q] = 0.0f;

    issue(0, 0);

    for (int kb = 0; kb < 16; kb++) {
        const int bufo = (kb & 1) * RC_STAGE;
        cp_wait<0>();
        __syncthreads();
        if (kb < 15) issue(kb + 1, RC_STAGE - bufo);

        const uint32_t bA = sb + bufo;
        const uint32_t bW = bA + 16384;
#pragma unroll
        for (int ks = 0; ks < 4; ks++) {
            uint32_t ah[2][4], bh[4][2];
#pragma unroll
            for (int mf = 0; mf < 2; mf++) {
                const uint32_t off = (uint32_t)(aRow[mf] * 128) +
                                     (((uint32_t)(ks * 32) + aKext) ^ aSw[mf]);
                ldm_x4(ah[mf][0], ah[mf][1], ah[mf][2], ah[mf][3], bA + off);
            }
#pragma unroll
            for (int p = 0; p < 2; p++) {
                const uint32_t off = (uint32_t)(bRow[p] * 128) +
                                     (((uint32_t)(ks * 32) + bKext) ^ bSw[p]);
                ldm_x4(bh[2 * p][0], bh[2 * p][1], bh[2 * p + 1][0], bh[2 * p + 1][1],
                       bW + off);
            }
#pragma unroll
            for (int mf = 0; mf < 2; mf++)
#pragma unroll
                for (int nf = 0; nf < 4; nf++)
                    mma16816(acc[mf][nf], ah[mf], bh[nf]);
        }
    }

    const int tr = lane >> 2;
    const int tc2 = (lane & 3) * 2;

    if (MODE == 0) {
#pragma unroll
        for (int mf = 0; mf < 2; mf++)
#pragma unroll
            for (int nf = 0; nf < 4; nf++) {
                const int n = n0 + wn + nf * 8 + tc2;
                const float bb0 = b0[n], bb1 = b0[n + 1];
                const int mA = m0 + wm + mf * 16 + tr;
                const int mB = mA + 8;
                float2 vA, vB;
                vA.x = acc[mf][nf][0] + bb0; vA.y = acc[mf][nf][1] + bb1;
                vB.x = acc[mf][nf][2] + bb0; vB.y = acc[mf][nf][3] + bb1;
                *(float2*)(C + (size_t)mA * Dc + n) = vA;
                *(float2*)(C + (size_t)mB * Dc + n) = vB;
            }
    } else {
        const int w = n0 >> 10;
        const int nl0 = n0 & 1023;
        const float scl = (w == 0) ? ATTN_SCALE : 1.0f;
        const float* bias = (w == 0) ? b0 : (w == 1) ? b1 : b2;
        __half* oh = (w == 0) ? qh : (w == 1) ? kh : vh;
#pragma unroll
        for (int mf = 0; mf < 2; mf++)
#pragma unroll
            for (int nf = 0; nf < 4; nf++) {
                const int n = nl0 + wn + nf * 8 + tc2;
                const float bb0 = bias[n], bb1 = bias[n + 1];
                const int mA = m0 + wm + mf * 16 + tr;
                const int mB = mA + 8;
                const float vA0 = (acc[mf][nf][0] + bb0) * scl;
                const float vA1 = (acc[mf][nf][1] + bb1) * scl;
                const float vB0 = (acc[mf][nf][2] + bb0) * scl;
                const float vB1 = (acc[mf][nf][3] + bb1) * scl;
                const int hh = n >> 6, hd = n & 63;
                const int bA = mA >> 11, tA = mA & 2047;
                const int bB = mB >> 11, tB = mB & 2047;
                const size_t oA = ((size_t)(bA * Hc + hh) * Tc + tA) * HDc + hd;
                const size_t oB = ((size_t)(bB * Hc + hh) * Tc + tB) * HDc + hd;
                *(__half2*)(oh + oA) = __floats2half2_rn(vA0, vA1);
                *(__half2*)(oh + oB) = __floats2half2_rn(vB0, vB1);
            }
    }
}

// ---------------------------------------------------------------------------
// Flash attention (fp16 1-term, R16 known-good). BQ=128, BKV=64.
// 2-stage KV pipeline; smem = Q 16K + 2 x (Kh 8K + Vh 8K) = 48 KB; 2 CTAs/SM.
// ---------------------------------------------------------------------------
#define FL_STAGE 16384
#define FL_SMEM (16384 + 2 * FL_STAGE)

__global__ void __launch_bounds__(256, 2)
flash_mma(const __half* __restrict__ Qh_, const __half* __restrict__ Kh_,
          const __half* __restrict__ Vh_, __half* __restrict__ Yh_)
{
    extern __shared__ char smem[];
    const uint32_t sb = smem_u32(smem);
    const int tid = threadIdx.x;
    const int lane = tid & 31;
    const int w = tid >> 5;
    const int qi = (int)(gridDim.x - 1) - (int)blockIdx.x;   // heavy tiles first
    const int q0 = qi * 128;
    const int h = blockIdx.y, b = blockIdx.z;
    const size_t base = (size_t)(b * Hc + h) * Tc * HDc;
    const __half* Qh = Qh_ + base;
    const __half* Kh = Kh_ + base;
    const __half* Vh = Vh_ + base;

    // Q tile (128 x 64) — first commit group
#pragma unroll
    for (int it = 0; it < 4; it++) {
        const int idx = it * 256 + tid;
        const int r = idx >> 3;
        const int ch = idx & 7;
        const uint32_t off = r * 128 + ((ch * 16) ^ ((r & 7) << 4));
        cp16(sb + off, Qh + (size_t)(q0 + r) * HDc + ch * 8);
    }
    cp_commit();

    auto issueKV = [&](int t) {
        const int k0 = t * 64;
        const uint32_t so = sb + 16384 + (t & 1) * FL_STAGE;
#pragma unroll
        for (int it = 0; it < 2; it++) {
            const int idx = it * 256 + tid;
            const int r = idx >> 3;
            const int ch = idx & 7;
            const uint32_t off = r * 128 + ((ch * 16) ^ ((r & 7) << 4));
            const size_t gi = (size_t)(k0 + r) * HDc + ch * 8;
            cp16(so + off,        Kh + gi);
            cp16(so + 8192 + off, Vh + gi);
        }
        cp_commit();
    };

    const int g = lane >> 3;
    const int lr = lane & 7;
    const int aRow = w * 16 + ((g & 1) ? 8 : 0) + lr;
    const uint32_t aSw = (uint32_t)((aRow & 7) << 4);
    const uint32_t aKext = (g >= 2) ? 16u : 0u;
    const int bRowBase = ((g >= 2) ? 8 : 0) + lr;
    const uint32_t bKext = (g & 1) ? 16u : 0u;
    const int vRow = lane & 15;
    const uint32_t vDext = (lane & 16) ? 16u : 0u;

    const int tr = lane >> 2;
    const int tc2 = (lane & 3) * 2;
    const int rowg0 = q0 + w * 16 + tr;
    const int rowg1 = rowg0 + 8;

    float mL[2] = { -INFINITY, -INFINITY };
    float lL[2] = { 0.0f, 0.0f };
    float o[8][4];
#pragma unroll
    for (int j = 0; j < 8; j++)
#pragma unroll
        for (int q = 0; q < 4; q++) o[j][q] = 0.0f;

    const int nt = q0 / 64 + 2;
    issueKV(0);

    for (int t = 0; t < nt; t++) {
        const int k0 = t * 64;
        cp_wait<0>();
        __syncthreads();
        if (t + 1 < nt) issueKV(t + 1);

        if (k0 <= q0 + w * 16 + 15) {
            const uint32_t so = sb + 16384 + (t & 1) * FL_STAGE;
            float s[8][4];
#pragma unroll
            for (int j = 0; j < 8; j++)
#pragma unroll
                for (int q = 0; q < 4; q++) s[j][q] = 0.0f;

            // S = Qh Kh^T
#pragma unroll
            for (int ks = 0; ks < 4; ks++) {
                uint32_t qh4[4];
                const uint32_t qoff = (uint32_t)(aRow * 128) +
                                      (((uint32_t)(ks * 32) + aKext) ^ aSw);
                ldm_x4(qh4[0], qh4[1], qh4[2], qh4[3], sb + qoff);
#pragma unroll
                for (int p = 0; p < 4; p++) {
                    const int row = p * 16 + bRowBase;
                    const uint32_t off = (uint32_t)(row * 128) +
                        (((uint32_t)(ks * 32) + bKext) ^ ((uint32_t)((row & 7) << 4)));
                    uint32_t kh2[2][2];
                    ldm_x4(kh2[0][0], kh2[0][1], kh2[1][0], kh2[1][1], so + off);
#pragma unroll
                    for (int u = 0; u < 2; u++)
                        mma16816(s[2 * p + u], qh4, kh2[u]);
                }
            }

            // Causal mask
            if (k0 + 63 > q0 + w * 16) {
#pragma unroll
                for (int j = 0; j < 8; j++) {
                    const int c = k0 + j * 8 + tc2;
                    if (c > rowg0)     s[j][0] = -INFINITY;
                    if (c + 1 > rowg0) s[j][1] = -INFINITY;
                    if (c > rowg1)     s[j][2] = -INFINITY;
                    if (c + 1 > rowg1) s[j][3] = -INFINITY;
                }
            }

            // Online softmax
#pragma unroll
            for (int half = 0; half < 2; half++) {
                const int i0 = half * 2;
                float mx = -INFINITY;
#pragma unroll
                for (int j = 0; j < 8; j++)
                    mx = fmaxf(mx, fmaxf(s[j][i0], s[j][i0 + 1]));
                mx = fmaxf(mx, __shfl_xor_sync(0xffffffffu, mx, 1));
                mx = fmaxf(mx, __shfl_xor_sync(0xffffffffu, mx, 2));
                const float mn = fmaxf(mL[half], mx);
                const float alpha = __expf(mL[half] - mn);
                float rs = 0.0f;
#pragma unroll
                for (int j = 0; j < 8; j++) {
                    const float p0 = __expf(s[j][i0] - mn);
                    const float p1 = __expf(s[j][i0 + 1] - mn);
                    s[j][i0] = p0; s[j][i0 + 1] = p1;
                    rs += p0 + p1;
                }
                rs += __shfl_xor_sync(0xffffffffu, rs, 1);
                rs += __shfl_xor_sync(0xffffffffu, rs, 2);
                lL[half] = lL[half] * alpha + rs;
                mL[half] = mn;
#pragma unroll
                for (int j = 0; j < 8; j++) {
                    o[j][i0] *= alpha;
                    o[j][i0 + 1] *= alpha;
                }
            }

            // O += Ph Vh
#pragma unroll
            for (int ks = 0; ks < 4; ks++) {
                const int j0 = 2 * ks, j1 = j0 + 1;
                uint32_t pha[4];
                pha[0] = pack_h2(s[j0][0], s[j0][1]);
                pha[1] = pack_h2(s[j0][2], s[j0][3]);
                pha[2] = pack_h2(s[j1][0], s[j1][1]);
                pha[3] = pack_h2(s[j1][2], s[j1][3]);
                const int vr = ks * 16 + vRow;
                const uint32_t vsw = (uint32_t)((vr & 7) << 4);
#pragma unroll
                for (int pp = 0; pp < 4; pp++) {
                    const uint32_t dbyte = (uint32_t)(pp * 32) + vDext;
                    const uint32_t off = (uint32_t)(vr * 128) + (dbyte ^ vsw);
                    uint32_t vh2[2][2];
                    ldm_x4t(vh2[0][0], vh2[0][1], vh2[1][0], vh2[1][1], so + 8192 + off);
#pragma unroll
                    for (int u = 0; u < 2; u++)
                        mma16816(o[2 * pp + u], pha, vh2[u]);
                }
            }
        }
    }

    // Epilogue: y (B,T,D) fp16 hi only
    const float inv0 = 1.0f / lL[0];
    const float inv1 = 1.0f / lL[1];
#pragma unroll
    for (int j = 0; j < 8; j++) {
        const int col = h * HDc + j * 8 + tc2;
        const size_t o0 = ((size_t)(b * Tc + rowg0)) * Dc + col;
        const size_t o1 = ((size_t)(b * Tc + rowg1)) * Dc + col;
        *(__half2*)(Yh_ + o0) = __floats2half2_rn(o[j][0] * inv0, o[j][1] * inv0);
        *(__half2*)(Yh_ + o1) = __floats2half2_rn(o[j][2] * inv1, o[j][3] * inv1);
    }
}

// ---------------------------------------------------------------------------
// Launch
// ---------------------------------------------------------------------------
extern "C" void kernel_launch(void* const* d_in, const int* in_sizes, int n_in,
                              void* d_out, int out_size)
{
    const float* x  = (const float*)d_in[0];
    // d_in[1]: boolean causal mask (applied analytically)
    const float* Wq = (const float*)d_in[2];
    const float* bq = (const float*)d_in[3];
    const float* Wk = (const float*)d_in[4];
    const float* bk = (const float*)d_in[5];
    const float* Wv = (const float*)d_in[6];
    const float* bv = (const float*)d_in[7];
    const float* Wo = (const float*)d_in[8];
    const float* bo = (const float*)d_in[9];
    float* out = (float*)d_out;

    __half *xh, *wh, *qh, *kh, *vh, *yh;
    cudaGetSymbolAddress((void**)&xh, g_xh);
    cudaGetSymbolAddress((void**)&wh, g_wh);
    cudaGetSymbolAddress((void**)&qh, g_qh);
    cudaGetSymbolAddress((void**)&kh, g_kh);
    cudaGetSymbolAddress((void**)&vh, g_vh);
    cudaGetSymbolAddress((void**)&yh, g_yh);

    cudaFuncSetAttribute(gemm_rc<0>, cudaFuncAttributeMaxDynamicSharedMemorySize, RC_SMEM);
    cudaFuncSetAttribute(gemm_rc<1>, cudaFuncAttributeMaxDynamicSharedMemorySize, RC_SMEM);
    cudaFuncSetAttribute(flash_mma, cudaFuncAttributeMaxDynamicSharedMemorySize, FL_SMEM);

    // Fused conversion: x + Wq,Wk,Wv,Wo -> fp16 hi
    split_all<<<(NX4 + 4 * NW4) / 256, 256>>>(x, Wq, Wk, Wv, Wo, xh, wh);

    // QKV as one flat N=3072 GEMM over concatenated weights (hi-only outputs)
    gemm_rc<1><<<dim3(3 * Dc / 64, Mc / 128), 256, RC_SMEM>>>(
        xh, wh, bq, bk, bv, nullptr, qh, kh, vh);

    flash_mma<<<dim3(Tc / 128, Hc, Bc), 256, FL_SMEM>>>(qh, kh, vh, yh);

    gemm_rc<0><<<dim3(Dc / 64, Mc / 128), 256, RC_SMEM>>>(
        yh, wh + 3 * (size_t)DD, bo, nullptr, nullptr, out,
        nullptr, nullptr, nullptr);
}